// round 1
// baseline (speedup 1.0000x reference)
#include <cuda_runtime.h>
#include <cstdint>

#define N_NODES 50000
#define N_EDGES 800000
#define D_F 256
#define D_H 512
#define D_O 256
#define D_AB 1024   // cols 0..511 = A (x@(W1a-W1b)+b1), cols 512..1023 = B (x@W1b)

// ---------------- scratch (static device allocations; no cudaMalloc) -------
__device__ float g_Wcat[D_F * D_AB];               // 1 MB
__device__ float g_AB[N_NODES * D_AB];             // 204.8 MB
__device__ float g_S[N_NODES * D_H];               // 102.4 MB
__device__ int   g_counts[N_NODES];
__device__ int   g_offsets[N_NODES + 1];
__device__ int   g_cursor[N_NODES];
__device__ int   g_scol[N_EDGES];
__device__ int   g_idx64;                          // 1 if edge_index is int64

// ---------------- edge-index dtype detection -------------------------------
// int64 node ids < 50000 -> every odd u32 word is 0. int32 -> odd words are
// real node ids (prob of 512 consecutive zeros ~ (1/50000)^512).
__global__ void detect_dtype_kernel(const unsigned* ei) {
    unsigned acc = 0;
    for (int k = threadIdx.x; k < 512; k += 32) acc |= ei[2 * k + 1];
    #pragma unroll
    for (int o = 16; o > 0; o >>= 1) acc |= __shfl_xor_sync(0xFFFFFFFFu, acc, o);
    if (threadIdx.x == 0) g_idx64 = (acc == 0) ? 1 : 0;
}

__device__ __forceinline__ int load_eidx(const void* ei, int is64, long long pos) {
    return is64 ? (int)((const long long*)ei)[pos] : ((const int*)ei)[pos];
}

// ---------------- W concat prep: Wcat[k][0:512]=W1a-W1b, [512:1024]=W1b -----
__global__ void build_wcat_kernel(const float* __restrict__ W1) {
    int idx = blockIdx.x * blockDim.x + threadIdx.x;
    if (idx < D_F * D_H) {
        int k = idx >> 9;          // 0..255
        int h = idx & 511;
        float wa = W1[k * D_H + h];
        float wb = W1[(k + D_F) * D_H + h];
        g_Wcat[k * D_AB + h]       = wa - wb;
        g_Wcat[k * D_AB + D_H + h] = wb;
    }
}

// ---------------- counting sort of edges by center node --------------------
__global__ void zero_counts_kernel() {
    int i = blockIdx.x * blockDim.x + threadIdx.x;
    if (i < N_NODES) g_counts[i] = 0;
}

__global__ void hist_kernel(const void* __restrict__ ei) {
    int e = blockIdx.x * blockDim.x + threadIdx.x;
    if (e >= N_EDGES) return;
    int r = load_eidx(ei, g_idx64, e);
    atomicAdd(&g_counts[r], 1);
}

// single-block exclusive scan over 50000 counts (Hillis-Steele per 1024 chunk)
__global__ void scan_kernel() {
    __shared__ int sh[1024];
    __shared__ int carry_s;
    int t = threadIdx.x;
    if (t == 0) carry_s = 0;
    __syncthreads();
    for (int base = 0; base < N_NODES; base += 1024) {
        int idx = base + t;
        int v = (idx < N_NODES) ? g_counts[idx] : 0;
        sh[t] = v;
        __syncthreads();
        #pragma unroll
        for (int off = 1; off < 1024; off <<= 1) {
            int add = (t >= off) ? sh[t - off] : 0;
            __syncthreads();
            sh[t] += add;
            __syncthreads();
        }
        int incl = sh[t];
        int carry = carry_s;
        int excl = carry + incl - v;
        if (idx < N_NODES) { g_offsets[idx] = excl; g_cursor[idx] = excl; }
        __syncthreads();
        if (t == 1023) carry_s = carry + incl;
        __syncthreads();
    }
    if (t == 0) g_offsets[N_NODES] = carry_s;
}

__global__ void scatter_kernel(const void* __restrict__ ei) {
    int e = blockIdx.x * blockDim.x + threadIdx.x;
    if (e >= N_EDGES) return;
    int is64 = g_idx64;
    int r = load_eidx(ei, is64, e);
    int c = load_eidx(ei, is64, (long long)N_EDGES + e);
    int pos = atomicAdd(&g_cursor[r], 1);
    g_scol[pos] = c;
}

// ---------------- fp32 SGEMM 128x128x8, 256 threads, 8x8 micro-tile --------
// mode 0: C = A@B, bias b added to cols < 512 (GEMM1: bias=b1)
// mode 1: C = A@B + deg[row]*b[col]          (GEMM2: bias=b2)
#define BM 128
#define BN 128
#define BK 8
#define TM 8
#define TN 8

__global__ __launch_bounds__(256) void sgemm_kernel(
    const float* __restrict__ A, const float* __restrict__ B,
    float* __restrict__ C, int M, int N, int K,
    const float* __restrict__ bias, int mode)
{
    __shared__ float As[BK][BM];
    __shared__ float Bs[BK][BN];
    int tid = threadIdx.x;
    int blockRow = blockIdx.y * BM;
    int blockCol = blockIdx.x * BN;

    int arow = tid >> 1;                 // 0..127
    int acol = (tid & 1) * 4;            // 0 or 4
    int brow = tid >> 5;                 // 0..7
    int bcol = (tid & 31) * 4;           // 0..124

    int ty = tid >> 4;                   // 0..15
    int tx = tid & 15;                   // 0..15

    float acc[TM][TN];
    #pragma unroll
    for (int m = 0; m < TM; m++)
        #pragma unroll
        for (int n = 0; n < TN; n++) acc[m][n] = 0.f;

    bool arowOK = (blockRow + arow) < M;
    const float* Aptr = A + (size_t)(blockRow + arow) * K + acol;
    const float* Bptr = B + (size_t)brow * N + blockCol + bcol;

    for (int k0 = 0; k0 < K; k0 += BK) {
        float4 av = arowOK ? *(const float4*)(Aptr + k0)
                           : make_float4(0.f, 0.f, 0.f, 0.f);
        As[acol + 0][arow] = av.x;
        As[acol + 1][arow] = av.y;
        As[acol + 2][arow] = av.z;
        As[acol + 3][arow] = av.w;
        *(float4*)&Bs[brow][bcol] = *(const float4*)(Bptr + (size_t)k0 * N);
        __syncthreads();

        #pragma unroll
        for (int kk = 0; kk < BK; kk++) {
            float ra[TM], rb[TN];
            *(float4*)&ra[0] = *(const float4*)&As[kk][ty * TM];
            *(float4*)&ra[4] = *(const float4*)&As[kk][ty * TM + 4];
            *(float4*)&rb[0] = *(const float4*)&Bs[kk][tx * TN];
            *(float4*)&rb[4] = *(const float4*)&Bs[kk][tx * TN + 4];
            #pragma unroll
            for (int m = 0; m < TM; m++)
                #pragma unroll
                for (int n = 0; n < TN; n++)
                    acc[m][n] = fmaf(ra[m], rb[n], acc[m][n]);
        }
        __syncthreads();
    }

    #pragma unroll
    for (int m = 0; m < TM; m++) {
        int row = blockRow + ty * TM + m;
        if (row >= M) continue;
        float degf = 0.f;
        if (mode == 1) degf = (float)(g_offsets[row + 1] - g_offsets[row]);
        #pragma unroll
        for (int n = 0; n < TN; n += 4) {
            int col = blockCol + tx * TN + n;
            float4 v = *(float4*)&acc[m][n];
            if (mode == 0) {
                if (col < 512) {
                    v.x += bias[col];     v.y += bias[col + 1];
                    v.z += bias[col + 2]; v.w += bias[col + 3];
                }
            } else {
                v.x += degf * bias[col];     v.y += degf * bias[col + 1];
                v.z += degf * bias[col + 2]; v.w += degf * bias[col + 3];
            }
            *(float4*)&C[(size_t)row * N + col] = v;
        }
    }
}

// ---------------- aggregation: S_i = sum_{j in N(i)} relu(A_i + B_j) -------
__global__ __launch_bounds__(128) void aggregate_kernel() {
    int i = blockIdx.x;
    int t = threadIdx.x;
    __shared__ int jbuf[128];

    const float4 a = *(const float4*)(g_AB + (size_t)i * D_AB + (t << 2));
    float4 s = make_float4(0.f, 0.f, 0.f, 0.f);

    int beg = g_offsets[i], end = g_offsets[i + 1];
    for (int base = beg; base < end; base += 128) {
        int cnt = min(128, end - base);
        if (t < cnt) jbuf[t] = g_scol[base + t];
        __syncthreads();
        int c = 0;
        for (; c + 1 < cnt; c += 2) {
            int j0 = jbuf[c], j1 = jbuf[c + 1];
            float4 b0 = *(const float4*)(g_AB + (size_t)j0 * D_AB + D_H + (t << 2));
            float4 b1 = *(const float4*)(g_AB + (size_t)j1 * D_AB + D_H + (t << 2));
            s.x += fmaxf(a.x + b0.x, 0.f) + fmaxf(a.x + b1.x, 0.f);
            s.y += fmaxf(a.y + b0.y, 0.f) + fmaxf(a.y + b1.y, 0.f);
            s.z += fmaxf(a.z + b0.z, 0.f) + fmaxf(a.z + b1.z, 0.f);
            s.w += fmaxf(a.w + b0.w, 0.f) + fmaxf(a.w + b1.w, 0.f);
        }
        if (c < cnt) {
            int j0 = jbuf[c];
            float4 b0 = *(const float4*)(g_AB + (size_t)j0 * D_AB + D_H + (t << 2));
            s.x += fmaxf(a.x + b0.x, 0.f);
            s.y += fmaxf(a.y + b0.y, 0.f);
            s.z += fmaxf(a.z + b0.z, 0.f);
            s.w += fmaxf(a.w + b0.w, 0.f);
        }
        __syncthreads();
    }
    *(float4*)(g_S + (size_t)i * D_H + (t << 2)) = s;
}

// ---------------- launcher --------------------------------------------------
extern "C" void kernel_launch(void* const* d_in, const int* in_sizes, int n_in,
                              void* d_out, int out_size) {
    const float* x   = (const float*)d_in[0];
    const void*  ei  = d_in[1];                 // int32 or int64, detected
    const float* W1  = (const float*)d_in[2];
    const float* b1  = (const float*)d_in[3];
    const float* W2  = (const float*)d_in[4];
    const float* b2  = (const float*)d_in[5];
    float* out = (float*)d_out;

    detect_dtype_kernel<<<1, 32>>>((const unsigned*)ei);
    build_wcat_kernel<<<(D_F * D_H + 255) / 256, 256>>>(W1);
    zero_counts_kernel<<<(N_NODES + 255) / 256, 256>>>();
    hist_kernel<<<(N_EDGES + 255) / 256, 256>>>(ei);
    scan_kernel<<<1, 1024>>>();
    scatter_kernel<<<(N_EDGES + 255) / 256, 256>>>(ei);

    // GEMM1: AB[50000,1024] = x[50000,256] @ Wcat[256,1024]  (+b1 on cols<512)
    {
        float* gAB; cudaGetSymbolAddress((void**)&gAB, g_AB);
        float* gW;  cudaGetSymbolAddress((void**)&gW,  g_Wcat);
        dim3 grid(D_AB / BN, (N_NODES + BM - 1) / BM);
        sgemm_kernel<<<grid, 256>>>(x, gW, gAB, N_NODES, D_AB, D_F, b1, 0);
    }

    aggregate_kernel<<<N_NODES, 128>>>();

    // GEMM2: out[50000,256] = S[50000,512] @ W2[512,256] + deg*b2
    {
        float* gS; cudaGetSymbolAddress((void**)&gS, g_S);
        dim3 grid(D_O / BN, (N_NODES + BM - 1) / BM);
        sgemm_kernel<<<grid, 256>>>(gS, W2, out, N_NODES, D_O, D_H, b2, 1);
    }
}

// round 3
// speedup vs baseline: 1.2594x; 1.2594x over previous
#include <cuda_runtime.h>
#include <cstdint>

#define N_NODES 50000
#define N_EDGES 800000
#define D_F 256
#define D_H 512
#define D_O 256
#define D_AB 1024   // cols 0..511 = A part (x@(W1a-W1b)+b1), 512..1023 = B part (x@W1b)

// ---------------- scratch (static device allocations; no cudaMalloc) -------
__device__ float g_WT1[D_AB * D_F];                // WcatT [1024][256] K-major, 1 MB
__device__ float g_WT2[D_O * D_H];                 // W2T   [256][512]  K-major, 0.5 MB
__device__ float g_bias1[D_AB];
__device__ float g_AB[N_NODES * D_AB];             // 204.8 MB
__device__ float g_S[N_NODES * D_H];               // 102.4 MB
__device__ int   g_counts[N_NODES];
__device__ int   g_offsets[N_NODES + 1];
__device__ int   g_cursor[N_NODES];
__device__ int   g_scol[N_EDGES];
__device__ int   g_idx64;

// ---------------- small helpers --------------------------------------------
__device__ __forceinline__ uint32_t f2tf32(float x) {
    uint32_t r;
    asm("cvt.rna.tf32.f32 %0, %1;" : "=r"(r) : "f"(x));
    return r;
}
__device__ __forceinline__ void mma_tf32(float* d, const uint32_t* a, const uint32_t* b) {
    asm volatile(
        "mma.sync.aligned.m16n8k8.row.col.f32.tf32.tf32.f32 "
        "{%0,%1,%2,%3}, {%4,%5,%6,%7}, {%8,%9}, {%0,%1,%2,%3};\n"
        : "+f"(d[0]), "+f"(d[1]), "+f"(d[2]), "+f"(d[3])
        : "r"(a[0]), "r"(a[1]), "r"(a[2]), "r"(a[3]), "r"(b[0]), "r"(b[1]));
}

// ---------------- edge-index dtype detection -------------------------------
__global__ void detect_dtype_kernel(const unsigned* ei) {
    unsigned acc = 0;
    for (int k = threadIdx.x; k < 512; k += 32) acc |= ei[2 * k + 1];
    #pragma unroll
    for (int o = 16; o > 0; o >>= 1) acc |= __shfl_xor_sync(0xFFFFFFFFu, acc, o);
    if (threadIdx.x == 0) g_idx64 = (acc == 0) ? 1 : 0;
}
__device__ __forceinline__ int load_eidx(const void* ei, int is64, long long pos) {
    return is64 ? (int)((const long long*)ei)[pos] : ((const int*)ei)[pos];
}

// ---------------- weight prep: transposed K-major operands -----------------
__global__ void build_w1t_kernel(const float* __restrict__ W1, const float* __restrict__ b1) {
    int idx = blockIdx.x * blockDim.x + threadIdx.x;
    if (idx < D_AB * D_F) {
        int n = idx >> 8;          // 0..1023
        int k = idx & 255;         // 0..255
        float v;
        if (n < D_H) v = W1[k * D_H + n] - W1[(k + D_F) * D_H + n];
        else         v = W1[(k + D_F) * D_H + (n - D_H)];
        g_WT1[n * D_F + k] = v;
    }
    if (idx < D_AB) g_bias1[idx] = (idx < D_H) ? b1[idx] : 0.f;
}
__global__ void build_w2t_kernel(const float* __restrict__ W2) {
    int idx = blockIdx.x * blockDim.x + threadIdx.x;
    if (idx < D_O * D_H) {
        int n = idx >> 9;          // 0..255
        int k = idx & 511;         // 0..511
        g_WT2[n * D_H + k] = W2[k * D_O + n];
    }
}

// ---------------- counting sort of edges by center node --------------------
__global__ void zero_counts_kernel() {
    int i = blockIdx.x * blockDim.x + threadIdx.x;
    if (i < N_NODES) g_counts[i] = 0;
}
__global__ void hist_kernel(const void* __restrict__ ei) {
    int e = blockIdx.x * blockDim.x + threadIdx.x;
    if (e >= N_EDGES) return;
    int r = load_eidx(ei, g_idx64, e);
    atomicAdd(&g_counts[r], 1);
}
__global__ void scan_kernel() {
    __shared__ int sh[1024];
    __shared__ int carry_s;
    int t = threadIdx.x;
    if (t == 0) carry_s = 0;
    __syncthreads();
    for (int base = 0; base < N_NODES; base += 1024) {
        int idx = base + t;
        int v = (idx < N_NODES) ? g_counts[idx] : 0;
        sh[t] = v;
        __syncthreads();
        #pragma unroll
        for (int off = 1; off < 1024; off <<= 1) {
            int add = (t >= off) ? sh[t - off] : 0;
            __syncthreads();
            sh[t] += add;
            __syncthreads();
        }
        int incl = sh[t];
        int carry = carry_s;
        int excl = carry + incl - v;
        if (idx < N_NODES) { g_offsets[idx] = excl; g_cursor[idx] = excl; }
        __syncthreads();
        if (t == 1023) carry_s = carry + incl;
        __syncthreads();
    }
    if (t == 0) g_offsets[N_NODES] = carry_s;
}
__global__ void scatter_kernel(const void* __restrict__ ei) {
    int e = blockIdx.x * blockDim.x + threadIdx.x;
    if (e >= N_EDGES) return;
    int is64 = g_idx64;
    int r = load_eidx(ei, is64, e);
    int c = load_eidx(ei, is64, (long long)N_EDGES + e);
    int pos = atomicAdd(&g_cursor[r], 1);
    g_scol[pos] = c;
}

// =================== mma.sync tf32 GEMM (error-compensated) ================
// C[M, Nglob] = A[M, K](lda) @ B^T  where B is [Nglob][K] K-major row-major.
// CTA tile 128x128, BK=32. 8 warps: 2(M) x 4(N), warp tile 64x32.
// Per warp: 4 m-tiles (m16) x 4 n-tiles (n8), mma m16n8k8, 3-term hi/lo.
// mode 0: C += bias[gcol]   mode 1: C += deg[row]*bias[gcol]
#define BK 32
#define STRIDE 36                         // 32 + 4 pad floats (conflict-free)
#define TILE_F (128 * STRIDE)             // 4608 floats per array
#define STAGE_F (4 * TILE_F)              // Ahi, Alo, Bhi, Blo
#define GEMM_DYNSMEM (2 * STAGE_F * 4)    // bytes

__global__ void __launch_bounds__(256) tc_gemm_kernel(
    const float* __restrict__ A, const float* __restrict__ B,
    float* __restrict__ C, int M, int lda, int K, int ldc,
    const float* __restrict__ bias, int mode)
{
    extern __shared__ float smem[];
    int tid = threadIdx.x;
    int wid = tid >> 5;
    int lane = tid & 31;
    int warpM = wid & 1;                  // 0..1
    int warpN = wid >> 1;                 // 0..3
    int blockRow = blockIdx.y * 128;
    int blockCol = blockIdx.x * 128;

    float acc[4][4][4];
    #pragma unroll
    for (int mt = 0; mt < 4; mt++)
        #pragma unroll
        for (int nt = 0; nt < 4; nt++)
            #pragma unroll
            for (int r = 0; r < 4; r++) acc[mt][nt][r] = 0.f;

    // gmem load mapping: 4 iters, each 256 threads cover 32 rows x 8 float4
    int ldRow = tid >> 3;                 // 0..31
    int ldC4  = tid & 7;                  // 0..7
    float4 ra[4], rb[4];

    const int nch = K >> 5;

    // ---- prologue: load chunk 0 ----
    #pragma unroll
    for (int it = 0; it < 4; it++) {
        int row = it * 32 + ldRow;
        int grow = blockRow + row;
        ra[it] = (grow < M) ? *(const float4*)(A + (size_t)grow * lda + ldC4 * 4)
                            : make_float4(0.f, 0.f, 0.f, 0.f);
        rb[it] = *(const float4*)(B + (size_t)(blockCol + row) * K + ldC4 * 4);
    }
    {
        float* sAhi = smem;
        float* sAlo = smem + TILE_F;
        float* sBhi = smem + 2 * TILE_F;
        float* sBlo = smem + 3 * TILE_F;
        #pragma unroll
        for (int it = 0; it < 4; it++) {
            int row = it * 32 + ldRow;
            int o = row * STRIDE + ldC4 * 4;
            float4 v = ra[it];
            float4 hi, lo;
            hi.x = __uint_as_float(f2tf32(v.x)); lo.x = v.x - hi.x;
            hi.y = __uint_as_float(f2tf32(v.y)); lo.y = v.y - hi.y;
            hi.z = __uint_as_float(f2tf32(v.z)); lo.z = v.z - hi.z;
            hi.w = __uint_as_float(f2tf32(v.w)); lo.w = v.w - hi.w;
            *(float4*)(sAhi + o) = hi; *(float4*)(sAlo + o) = lo;
            v = rb[it];
            hi.x = __uint_as_float(f2tf32(v.x)); lo.x = v.x - hi.x;
            hi.y = __uint_as_float(f2tf32(v.y)); lo.y = v.y - hi.y;
            hi.z = __uint_as_float(f2tf32(v.z)); lo.z = v.z - hi.z;
            hi.w = __uint_as_float(f2tf32(v.w)); lo.w = v.w - hi.w;
            *(float4*)(sBhi + o) = hi; *(float4*)(sBlo + o) = lo;
        }
    }
    __syncthreads();

    int aRow0 = warpM * 64 + (lane >> 2);     // + mt*16 (+8)
    int bCol0 = warpN * 32 + (lane >> 2);     // + nt*8
    int kLane = lane & 3;

    for (int c = 0; c < nch; c++) {
        // issue gmem loads for next chunk
        if (c + 1 < nch) {
            int k0 = (c + 1) << 5;
            #pragma unroll
            for (int it = 0; it < 4; it++) {
                int row = it * 32 + ldRow;
                int grow = blockRow + row;
                ra[it] = (grow < M) ? *(const float4*)(A + (size_t)grow * lda + k0 + ldC4 * 4)
                                    : make_float4(0.f, 0.f, 0.f, 0.f);
                rb[it] = *(const float4*)(B + (size_t)(blockCol + row) * K + k0 + ldC4 * 4);
            }
        }

        // compute on buffer c&1
        {
            const float* base = smem + (c & 1) * STAGE_F;
            const float* sAhi = base;
            const float* sAlo = base + TILE_F;
            const float* sBhi = base + 2 * TILE_F;
            const float* sBlo = base + 3 * TILE_F;
            #pragma unroll
            for (int ks = 0; ks < 4; ks++) {
                int k = ks * 8 + kLane;
                uint32_t ahi[4][4], alo[4][4], bhi[4][2], blo[4][2];
                #pragma unroll
                for (int mt = 0; mt < 4; mt++) {
                    int r = aRow0 + mt * 16;
                    ahi[mt][0] = __float_as_uint(sAhi[r * STRIDE + k]);
                    ahi[mt][1] = __float_as_uint(sAhi[(r + 8) * STRIDE + k]);
                    ahi[mt][2] = __float_as_uint(sAhi[r * STRIDE + k + 4]);
                    ahi[mt][3] = __float_as_uint(sAhi[(r + 8) * STRIDE + k + 4]);
                    alo[mt][0] = f2tf32(sAlo[r * STRIDE + k]);
                    alo[mt][1] = f2tf32(sAlo[(r + 8) * STRIDE + k]);
                    alo[mt][2] = f2tf32(sAlo[r * STRIDE + k + 4]);
                    alo[mt][3] = f2tf32(sAlo[(r + 8) * STRIDE + k + 4]);
                }
                #pragma unroll
                for (int nt = 0; nt < 4; nt++) {
                    int n = bCol0 + nt * 8;
                    bhi[nt][0] = __float_as_uint(sBhi[n * STRIDE + k]);
                    bhi[nt][1] = __float_as_uint(sBhi[n * STRIDE + k + 4]);
                    blo[nt][0] = f2tf32(sBlo[n * STRIDE + k]);
                    blo[nt][1] = f2tf32(sBlo[n * STRIDE + k + 4]);
                }
                #pragma unroll
                for (int mt = 0; mt < 4; mt++)
                    #pragma unroll
                    for (int nt = 0; nt < 4; nt++) {
                        mma_tf32(acc[mt][nt], ahi[mt], bhi[nt]);
                        mma_tf32(acc[mt][nt], ahi[mt], blo[nt]);
                        mma_tf32(acc[mt][nt], alo[mt], bhi[nt]);
                    }
            }
        }

        if (c + 1 < nch) {
            __syncthreads();   // everyone done reading buf (c+1)&1 (used at c-1)
            float* base = smem + ((c + 1) & 1) * STAGE_F;
            float* sAhi = base;
            float* sAlo = base + TILE_F;
            float* sBhi = base + 2 * TILE_F;
            float* sBlo = base + 3 * TILE_F;
            #pragma unroll
            for (int it = 0; it < 4; it++) {
                int row = it * 32 + ldRow;
                int o = row * STRIDE + ldC4 * 4;
                float4 v = ra[it];
                float4 hi, lo;
                hi.x = __uint_as_float(f2tf32(v.x)); lo.x = v.x - hi.x;
                hi.y = __uint_as_float(f2tf32(v.y)); lo.y = v.y - hi.y;
                hi.z = __uint_as_float(f2tf32(v.z)); lo.z = v.z - hi.z;
                hi.w = __uint_as_float(f2tf32(v.w)); lo.w = v.w - hi.w;
                *(float4*)(sAhi + o) = hi; *(float4*)(sAlo + o) = lo;
                v = rb[it];
                hi.x = __uint_as_float(f2tf32(v.x)); lo.x = v.x - hi.x;
                hi.y = __uint_as_float(f2tf32(v.y)); lo.y = v.y - hi.y;
                hi.z = __uint_as_float(f2tf32(v.z)); lo.z = v.z - hi.z;
                hi.w = __uint_as_float(f2tf32(v.w)); lo.w = v.w - hi.w;
                *(float4*)(sBhi + o) = hi; *(float4*)(sBlo + o) = lo;
            }
            __syncthreads();
        }
    }

    // ---- epilogue ----
    #pragma unroll
    for (int mt = 0; mt < 4; mt++) {
        int r0 = blockRow + warpM * 64 + mt * 16 + (lane >> 2);
        int r1 = r0 + 8;
        float deg0 = 0.f, deg1 = 0.f;
        if (mode == 1) {
            if (r0 < M) deg0 = (float)(g_offsets[r0 + 1] - g_offsets[r0]);
            if (r1 < M) deg1 = (float)(g_offsets[r1 + 1] - g_offsets[r1]);
        }
        #pragma unroll
        for (int nt = 0; nt < 4; nt++) {
            int col = blockCol + warpN * 32 + nt * 8 + (lane & 3) * 2;
            float b0 = bias[col], b1v = bias[col + 1];
            if (r0 < M) {
                float2 v;
                if (mode == 0) { v.x = acc[mt][nt][0] + b0; v.y = acc[mt][nt][1] + b1v; }
                else           { v.x = acc[mt][nt][0] + deg0 * b0; v.y = acc[mt][nt][1] + deg0 * b1v; }
                *(float2*)(C + (size_t)r0 * ldc + col) = v;
            }
            if (r1 < M) {
                float2 v;
                if (mode == 0) { v.x = acc[mt][nt][2] + b0; v.y = acc[mt][nt][3] + b1v; }
                else           { v.x = acc[mt][nt][2] + deg1 * b0; v.y = acc[mt][nt][3] + deg1 * b1v; }
                *(float2*)(C + (size_t)r1 * ldc + col) = v;
            }
        }
    }
}

// ---------------- aggregation: S_i = sum_{j in N(i)} relu(A_i + B_j) -------
__global__ __launch_bounds__(128) void aggregate_kernel() {
    int i = blockIdx.x;
    int t = threadIdx.x;
    __shared__ int jbuf[128];

    const float4 a = *(const float4*)(g_AB + (size_t)i * D_AB + (t << 2));
    float4 s = make_float4(0.f, 0.f, 0.f, 0.f);

    int beg = g_offsets[i], end = g_offsets[i + 1];
    for (int base = beg; base < end; base += 128) {
        int cnt = min(128, end - base);
        if (t < cnt) jbuf[t] = g_scol[base + t];
        __syncthreads();
        int c = 0;
        for (; c + 1 < cnt; c += 2) {
            int j0 = jbuf[c], j1 = jbuf[c + 1];
            float4 b0 = *(const float4*)(g_AB + (size_t)j0 * D_AB + D_H + (t << 2));
            float4 b1 = *(const float4*)(g_AB + (size_t)j1 * D_AB + D_H + (t << 2));
            s.x += fmaxf(a.x + b0.x, 0.f) + fmaxf(a.x + b1.x, 0.f);
            s.y += fmaxf(a.y + b0.y, 0.f) + fmaxf(a.y + b1.y, 0.f);
            s.z += fmaxf(a.z + b0.z, 0.f) + fmaxf(a.z + b1.z, 0.f);
            s.w += fmaxf(a.w + b0.w, 0.f) + fmaxf(a.w + b1.w, 0.f);
        }
        if (c < cnt) {
            int j0 = jbuf[c];
            float4 b0 = *(const float4*)(g_AB + (size_t)j0 * D_AB + D_H + (t << 2));
            s.x += fmaxf(a.x + b0.x, 0.f);
            s.y += fmaxf(a.y + b0.y, 0.f);
            s.z += fmaxf(a.z + b0.z, 0.f);
            s.w += fmaxf(a.w + b0.w, 0.f);
        }
        __syncthreads();
    }
    *(float4*)(g_S + (size_t)i * D_H + (t << 2)) = s;
}

// ---------------- launcher --------------------------------------------------
extern "C" void kernel_launch(void* const* d_in, const int* in_sizes, int n_in,
                              void* d_out, int out_size) {
    const float* x   = (const float*)d_in[0];
    const void*  ei  = d_in[1];
    const float* W1  = (const float*)d_in[2];
    const float* b1  = (const float*)d_in[3];
    const float* W2  = (const float*)d_in[4];
    const float* b2  = (const float*)d_in[5];
    float* out = (float*)d_out;

    cudaFuncSetAttribute(tc_gemm_kernel,
                         cudaFuncAttributeMaxDynamicSharedMemorySize, GEMM_DYNSMEM);

    detect_dtype_kernel<<<1, 32>>>((const unsigned*)ei);
    build_w1t_kernel<<<(D_AB * D_F + 255) / 256, 256>>>(W1, b1);
    build_w2t_kernel<<<(D_O * D_H + 255) / 256, 256>>>(W2);
    zero_counts_kernel<<<(N_NODES + 255) / 256, 256>>>();
    hist_kernel<<<(N_EDGES + 255) / 256, 256>>>(ei);
    scan_kernel<<<1, 1024>>>();
    scatter_kernel<<<(N_EDGES + 255) / 256, 256>>>(ei);

    float *gAB, *gS, *gWT1, *gWT2, *gB1;
    cudaGetSymbolAddress((void**)&gAB,  g_AB);
    cudaGetSymbolAddress((void**)&gS,   g_S);
    cudaGetSymbolAddress((void**)&gWT1, g_WT1);
    cudaGetSymbolAddress((void**)&gWT2, g_WT2);
    cudaGetSymbolAddress((void**)&gB1,  g_bias1);

    // GEMM1: AB[50000,1024] = x[50000,256] @ WT1^T (+bias_cat)
    {
        dim3 grid(D_AB / 128, (N_NODES + 127) / 128);
        tc_gemm_kernel<<<grid, 256, GEMM_DYNSMEM>>>(
            x, gWT1, gAB, N_NODES, D_F, D_F, D_AB, gB1, 0);
    }

    aggregate_kernel<<<N_NODES, 128>>>();

    // GEMM2: out[50000,256] = S[50000,512] @ WT2^T + deg*b2
    {
        dim3 grid(D_O / 128, (N_NODES + 127) / 128);
        tc_gemm_kernel<<<grid, 256, GEMM_DYNSMEM>>>(
            gS, gWT2, out, N_NODES, D_H, D_H, D_O, b2, 1);
    }
}

// round 4
// speedup vs baseline: 1.3688x; 1.0869x over previous
#include <cuda_runtime.h>
#include <cuda_bf16.h>
#include <cstdint>

#define N_NODES 50000
#define N_EDGES 800000
#define D_F 256
#define D_H 512
#define D_O 256
#define D_AB 1024   // cols 0..511 = A part (x@(W1a-W1b)+b1), 512..1023 = B part (x@W1b)

// ---------------- scratch (static device allocations; no cudaMalloc) -------
__device__ uint32_t g_WT1hi[D_AB * (D_F / 2)];     // packed bf16 pairs, K-major
__device__ uint32_t g_WT1lo[D_AB * (D_F / 2)];
__device__ uint32_t g_WT2hi[D_O * (D_H / 2)];
__device__ uint32_t g_WT2lo[D_O * (D_H / 2)];
__device__ float    g_bias1[D_AB];
__device__ float    g_AB[N_NODES * D_AB];          // 204.8 MB fp32
__device__ uint32_t g_Shi[N_NODES * (D_H / 2)];    // 51.2 MB packed bf16
__device__ uint32_t g_Slo[N_NODES * (D_H / 2)];
__device__ int      g_counts[N_NODES];
__device__ int      g_offsets[N_NODES + 1];
__device__ int      g_cursor[N_NODES];
__device__ int      g_scol[N_EDGES];
__device__ int      g_idx64;

// ---------------- helpers ---------------------------------------------------
// pack two floats into bf16x2 hi word + bf16x2 lo (residual) word.
// low 16 bits = even-k element (mma fragment convention).
__device__ __forceinline__ void split2(float v0, float v1, uint32_t& hw, uint32_t& lw) {
    __nv_bfloat16 h0 = __float2bfloat16_rn(v0);
    __nv_bfloat16 h1 = __float2bfloat16_rn(v1);
    float r0 = v0 - __bfloat162float(h0);
    float r1 = v1 - __bfloat162float(h1);
    __nv_bfloat16 l0 = __float2bfloat16_rn(r0);
    __nv_bfloat16 l1 = __float2bfloat16_rn(r1);
    hw = (uint32_t)__bfloat16_as_ushort(h0) | ((uint32_t)__bfloat16_as_ushort(h1) << 16);
    lw = (uint32_t)__bfloat16_as_ushort(l0) | ((uint32_t)__bfloat16_as_ushort(l1) << 16);
}
__device__ __forceinline__ void mma_bf16(float* d, const uint32_t* a, const uint32_t* b) {
    asm volatile(
        "mma.sync.aligned.m16n8k16.row.col.f32.bf16.bf16.f32 "
        "{%0,%1,%2,%3}, {%4,%5,%6,%7}, {%8,%9}, {%0,%1,%2,%3};\n"
        : "+f"(d[0]), "+f"(d[1]), "+f"(d[2]), "+f"(d[3])
        : "r"(a[0]), "r"(a[1]), "r"(a[2]), "r"(a[3]), "r"(b[0]), "r"(b[1]));
}

// ---------------- edge-index dtype detection -------------------------------
__global__ void detect_dtype_kernel(const unsigned* ei) {
    unsigned acc = 0;
    for (int k = threadIdx.x; k < 512; k += 32) acc |= ei[2 * k + 1];
    #pragma unroll
    for (int o = 16; o > 0; o >>= 1) acc |= __shfl_xor_sync(0xFFFFFFFFu, acc, o);
    if (threadIdx.x == 0) g_idx64 = (acc == 0) ? 1 : 0;
}
__device__ __forceinline__ int load_eidx(const void* ei, int is64, long long pos) {
    return is64 ? (int)((const long long*)ei)[pos] : ((const int*)ei)[pos];
}

// ---------------- weight prep: K-major packed bf16 hi/lo -------------------
__global__ void build_w1t_kernel(const float* __restrict__ W1, const float* __restrict__ b1) {
    int idx = blockIdx.x * blockDim.x + threadIdx.x;
    if (idx < D_AB * (D_F / 2)) {
        int n  = idx >> 7;            // 0..1023
        int kw = idx & 127;           // 0..127
        int k0 = kw * 2;
        float v0, v1;
        if (n < D_H) {
            v0 = W1[k0 * D_H + n]       - W1[(k0 + D_F) * D_H + n];
            v1 = W1[(k0 + 1) * D_H + n] - W1[(k0 + 1 + D_F) * D_H + n];
        } else {
            v0 = W1[(k0 + D_F) * D_H + (n - D_H)];
            v1 = W1[(k0 + 1 + D_F) * D_H + (n - D_H)];
        }
        uint32_t hw, lw;
        split2(v0, v1, hw, lw);
        g_WT1hi[idx] = hw; g_WT1lo[idx] = lw;
    }
    if (idx < D_AB) g_bias1[idx] = (idx < D_H) ? b1[idx] : 0.f;
}
__global__ void build_w2t_kernel(const float* __restrict__ W2) {
    int idx = blockIdx.x * blockDim.x + threadIdx.x;
    if (idx < D_O * (D_H / 2)) {
        int n  = idx >> 8;            // 0..255
        int kw = idx & 255;           // 0..255
        float v0 = W2[(2 * kw) * D_O + n];
        float v1 = W2[(2 * kw + 1) * D_O + n];
        uint32_t hw, lw;
        split2(v0, v1, hw, lw);
        g_WT2hi[idx] = hw; g_WT2lo[idx] = lw;
    }
}

// ---------------- counting sort of edges by center node --------------------
__global__ void zero_counts_kernel() {
    int i = blockIdx.x * blockDim.x + threadIdx.x;
    if (i < N_NODES) g_counts[i] = 0;
}
__global__ void hist_kernel(const void* __restrict__ ei) {
    int e = blockIdx.x * blockDim.x + threadIdx.x;
    if (e >= N_EDGES) return;
    int r = load_eidx(ei, g_idx64, e);
    atomicAdd(&g_counts[r], 1);
}
// per-thread serial (49 elems) + single block scan of 1024 partials
__global__ void scan_kernel() {
    __shared__ int sh[1024];
    const int PER = 49;               // 1024*49 = 50176 >= 50000
    int t = threadIdx.x;
    int base = t * PER;
    int sum = 0;
    for (int j = 0; j < PER; j++) {
        int idx = base + j;
        if (idx < N_NODES) sum += g_counts[idx];
    }
    sh[t] = sum;
    __syncthreads();
    #pragma unroll
    for (int off = 1; off < 1024; off <<= 1) {
        int add = (t >= off) ? sh[t - off] : 0;
        __syncthreads();
        sh[t] += add;
        __syncthreads();
    }
    int run = sh[t] - sum;            // exclusive prefix of this thread's range
    for (int j = 0; j < PER; j++) {
        int idx = base + j;
        if (idx < N_NODES) {
            g_offsets[idx] = run;
            g_cursor[idx]  = run;
            run += g_counts[idx];
        }
    }
    if (t == 1023) g_offsets[N_NODES] = run;
}
__global__ void scatter_kernel(const void* __restrict__ ei) {
    int e = blockIdx.x * blockDim.x + threadIdx.x;
    if (e >= N_EDGES) return;
    int is64 = g_idx64;
    int r = load_eidx(ei, is64, e);
    int c = load_eidx(ei, is64, (long long)N_EDGES + e);
    int pos = atomicAdd(&g_cursor[r], 1);
    g_scol[pos] = c;
}

// =================== mma.sync bf16 GEMM (error-compensated 3-term) =========
// C[M,N] = A[M,K] @ B^T, B given as packed bf16 hi/lo [N][K/2] K-major words.
// A either fp32 [M][K] (split on the fly) or packed hi/lo words [M][K/2].
// CTA tile 128x128, BK=32 (16 words). 8 warps 2(M)x4(N), warp tile 64x32.
// mode 0: C += bias[col]   mode 1: C += deg[row]*bias[col]
#define KWC 16                          // words per row per chunk
#define STW 20                          // smem row stride in words (16+4 pad)
#define TILE_W (128 * STW)              // 2560 words
#define STAGE_W (4 * TILE_W)            // Ahi, Alo, Bhi, Blo
#define GEMM_DYNSMEM (2 * STAGE_W * 4)  // 81920 bytes

__global__ void __launch_bounds__(256) tc_gemm_kernel(
    const float* __restrict__ Af,
    const uint32_t* __restrict__ Ahi, const uint32_t* __restrict__ Alo, int aPacked,
    const uint32_t* __restrict__ Bhi, const uint32_t* __restrict__ Blo,
    float* __restrict__ C, int M, int K, int ldc,
    const float* __restrict__ bias, int mode)
{
    extern __shared__ uint32_t smw[];
    int tid = threadIdx.x;
    int wid = tid >> 5;
    int lane = tid & 31;
    int warpM = wid & 1;
    int warpN = wid >> 1;
    int blockRow = blockIdx.y * 128;
    int blockCol = blockIdx.x * 128;
    const int Kw = K >> 1;
    const int nch = K >> 5;

    float acc[4][4][4];
    #pragma unroll
    for (int mt = 0; mt < 4; mt++)
        #pragma unroll
        for (int nt = 0; nt < 4; nt++)
            #pragma unroll
            for (int r = 0; r < 4; r++) acc[mt][nt][r] = 0.f;

    // load mapping: thread -> (row, half); each thread owns 8 words (16 floats)
    int ldRow = tid >> 1;               // 0..127
    int ldHalf = tid & 1;               // 0..1
    int so = ldRow * STW + ldHalf * 8;  // smem word offset (16B aligned)
    int grow = blockRow + ldRow;
    bool rowOK = grow < M;
    int brow = blockCol + ldRow;

    float4 ra[4];                       // fp32-A prefetch
    uint4 pah[2], pal[2];               // packed-A prefetch
    uint4 pbh[2], pbl[2];               // B prefetch

    // ---- helper lambdas (inlined) ----
    auto storeA_fp32 = [&](uint32_t* base) {
        uint32_t* sAhi = base;
        uint32_t* sAlo = base + TILE_W;
        uint4 hh0, hh1, ll0, ll1;
        split2(ra[0].x, ra[0].y, hh0.x, ll0.x);
        split2(ra[0].z, ra[0].w, hh0.y, ll0.y);
        split2(ra[1].x, ra[1].y, hh0.z, ll0.z);
        split2(ra[1].z, ra[1].w, hh0.w, ll0.w);
        split2(ra[2].x, ra[2].y, hh1.x, ll1.x);
        split2(ra[2].z, ra[2].w, hh1.y, ll1.y);
        split2(ra[3].x, ra[3].y, hh1.z, ll1.z);
        split2(ra[3].z, ra[3].w, hh1.w, ll1.w);
        *(uint4*)(sAhi + so) = hh0; *(uint4*)(sAhi + so + 4) = hh1;
        *(uint4*)(sAlo + so) = ll0; *(uint4*)(sAlo + so + 4) = ll1;
    };
    auto storeA_packed = [&](uint32_t* base) {
        uint32_t* sAhi = base;
        uint32_t* sAlo = base + TILE_W;
        *(uint4*)(sAhi + so) = pah[0]; *(uint4*)(sAhi + so + 4) = pah[1];
        *(uint4*)(sAlo + so) = pal[0]; *(uint4*)(sAlo + so + 4) = pal[1];
    };
    auto storeB = [&](uint32_t* base) {
        uint32_t* sBhi = base + 2 * TILE_W;
        uint32_t* sBlo = base + 3 * TILE_W;
        *(uint4*)(sBhi + so) = pbh[0]; *(uint4*)(sBhi + so + 4) = pbh[1];
        *(uint4*)(sBlo + so) = pbl[0]; *(uint4*)(sBlo + so + 4) = pbl[1];
    };
    auto fetch = [&](int c) {
        if (aPacked) {
            if (rowOK) {
                const uint4* ph = (const uint4*)(Ahi + (size_t)grow * Kw + c * KWC + ldHalf * 8);
                const uint4* pl = (const uint4*)(Alo + (size_t)grow * Kw + c * KWC + ldHalf * 8);
                pah[0] = ph[0]; pah[1] = ph[1];
                pal[0] = pl[0]; pal[1] = pl[1];
            } else {
                pah[0] = pah[1] = pal[0] = pal[1] = make_uint4(0, 0, 0, 0);
            }
        } else {
            if (rowOK) {
                const float4* p = (const float4*)(Af + (size_t)grow * K + c * 32 + ldHalf * 16);
                ra[0] = p[0]; ra[1] = p[1]; ra[2] = p[2]; ra[3] = p[3];
            } else {
                ra[0] = ra[1] = ra[2] = ra[3] = make_float4(0.f, 0.f, 0.f, 0.f);
            }
        }
        const uint4* qh = (const uint4*)(Bhi + (size_t)brow * Kw + c * KWC + ldHalf * 8);
        const uint4* ql = (const uint4*)(Blo + (size_t)brow * Kw + c * KWC + ldHalf * 8);
        pbh[0] = qh[0]; pbh[1] = qh[1];
        pbl[0] = ql[0]; pbl[1] = ql[1];
    };

    // ---- prologue: chunk 0 ----
    fetch(0);
    if (aPacked) storeA_packed(smw); else storeA_fp32(smw);
    storeB(smw);
    __syncthreads();

    int aRow0 = warpM * 64 + (lane >> 2);
    int bCol0 = warpN * 32 + (lane >> 2);
    int kl = lane & 3;

    for (int c = 0; c < nch; c++) {
        if (c + 1 < nch) fetch(c + 1);

        const uint32_t* base = smw + (c & 1) * STAGE_W;
        const uint32_t* sAhi = base;
        const uint32_t* sAlo = base + TILE_W;
        const uint32_t* sBhi = base + 2 * TILE_W;
        const uint32_t* sBlo = base + 3 * TILE_W;

        #pragma unroll
        for (int ks = 0; ks < 2; ks++) {
            int kw = ks * 8 + kl;
            uint32_t ahi[4][4], alo[4][4], bhi[4][2], blo[4][2];
            #pragma unroll
            for (int mt = 0; mt < 4; mt++) {
                int r = aRow0 + mt * 16;
                ahi[mt][0] = sAhi[r * STW + kw];
                ahi[mt][1] = sAhi[(r + 8) * STW + kw];
                ahi[mt][2] = sAhi[r * STW + kw + 4];
                ahi[mt][3] = sAhi[(r + 8) * STW + kw + 4];
                alo[mt][0] = sAlo[r * STW + kw];
                alo[mt][1] = sAlo[(r + 8) * STW + kw];
                alo[mt][2] = sAlo[r * STW + kw + 4];
                alo[mt][3] = sAlo[(r + 8) * STW + kw + 4];
            }
            #pragma unroll
            for (int nt = 0; nt < 4; nt++) {
                int n = bCol0 + nt * 8;
                bhi[nt][0] = sBhi[n * STW + kw];
                bhi[nt][1] = sBhi[n * STW + kw + 4];
                blo[nt][0] = sBlo[n * STW + kw];
                blo[nt][1] = sBlo[n * STW + kw + 4];
            }
            #pragma unroll
            for (int mt = 0; mt < 4; mt++)
                #pragma unroll
                for (int nt = 0; nt < 4; nt++) {
                    mma_bf16(acc[mt][nt], ahi[mt], bhi[nt]);
                    mma_bf16(acc[mt][nt], ahi[mt], blo[nt]);
                    mma_bf16(acc[mt][nt], alo[mt], bhi[nt]);
                }
        }

        if (c + 1 < nch) {
            __syncthreads();
            uint32_t* nbase = smw + ((c + 1) & 1) * STAGE_W;
            if (aPacked) storeA_packed(nbase); else storeA_fp32(nbase);
            storeB(nbase);
            __syncthreads();
        }
    }

    // ---- epilogue ----
    #pragma unroll
    for (int mt = 0; mt < 4; mt++) {
        int r0 = blockRow + warpM * 64 + mt * 16 + (lane >> 2);
        int r1 = r0 + 8;
        float deg0 = 0.f, deg1 = 0.f;
        if (mode == 1) {
            if (r0 < M) deg0 = (float)(g_offsets[r0 + 1] - g_offsets[r0]);
            if (r1 < M) deg1 = (float)(g_offsets[r1 + 1] - g_offsets[r1]);
        }
        #pragma unroll
        for (int nt = 0; nt < 4; nt++) {
            int col = blockCol + warpN * 32 + nt * 8 + (lane & 3) * 2;
            float b0 = bias[col], b1v = bias[col + 1];
            if (r0 < M) {
                float2 v;
                if (mode == 0) { v.x = acc[mt][nt][0] + b0;        v.y = acc[mt][nt][1] + b1v; }
                else           { v.x = acc[mt][nt][0] + deg0 * b0; v.y = acc[mt][nt][1] + deg0 * b1v; }
                *(float2*)(C + (size_t)r0 * ldc + col) = v;
            }
            if (r1 < M) {
                float2 v;
                if (mode == 0) { v.x = acc[mt][nt][2] + b0;        v.y = acc[mt][nt][3] + b1v; }
                else           { v.x = acc[mt][nt][2] + deg1 * b0; v.y = acc[mt][nt][3] + deg1 * b1v; }
                *(float2*)(C + (size_t)r1 * ldc + col) = v;
            }
        }
    }
}

// ---------------- aggregation: S_i = sum_j relu(A_i + B_j), warp per node --
// outputs packed bf16 hi/lo words (GEMM2 A operand).
__global__ __launch_bounds__(256) void aggregate_kernel() {
    int gw = (blockIdx.x * blockDim.x + threadIdx.x) >> 5;   // node id
    int lane = threadIdx.x & 31;
    if (gw >= N_NODES) return;

    const float4* Ai = (const float4*)(g_AB + (size_t)gw * D_AB) + lane * 4;
    float4 a0 = Ai[0], a1 = Ai[1], a2 = Ai[2], a3 = Ai[3];
    float4 s0 = make_float4(0, 0, 0, 0), s1 = s0, s2 = s0, s3 = s0;

    int beg = g_offsets[gw], end = g_offsets[gw + 1];
    for (int b = beg; b < end; b += 32) {
        int jv = (b + lane < end) ? g_scol[b + lane] : 0;
        int cnt = min(32, end - b);
        int t = 0;
        for (; t + 1 < cnt; t += 2) {
            int j0 = __shfl_sync(0xFFFFFFFFu, jv, t);
            int j1 = __shfl_sync(0xFFFFFFFFu, jv, t + 1);
            const float4* B0 = (const float4*)(g_AB + (size_t)j0 * D_AB + D_H) + lane * 4;
            const float4* B1 = (const float4*)(g_AB + (size_t)j1 * D_AB + D_H) + lane * 4;
            float4 p0 = B0[0], p1 = B0[1], p2 = B0[2], p3 = B0[3];
            float4 q0 = B1[0], q1 = B1[1], q2 = B1[2], q3 = B1[3];
            s0.x += fmaxf(a0.x + p0.x, 0.f) + fmaxf(a0.x + q0.x, 0.f);
            s0.y += fmaxf(a0.y + p0.y, 0.f) + fmaxf(a0.y + q0.y, 0.f);
            s0.z += fmaxf(a0.z + p0.z, 0.f) + fmaxf(a0.z + q0.z, 0.f);
            s0.w += fmaxf(a0.w + p0.w, 0.f) + fmaxf(a0.w + q0.w, 0.f);
            s1.x += fmaxf(a1.x + p1.x, 0.f) + fmaxf(a1.x + q1.x, 0.f);
            s1.y += fmaxf(a1.y + p1.y, 0.f) + fmaxf(a1.y + q1.y, 0.f);
            s1.z += fmaxf(a1.z + p1.z, 0.f) + fmaxf(a1.z + q1.z, 0.f);
            s1.w += fmaxf(a1.w + p1.w, 0.f) + fmaxf(a1.w + q1.w, 0.f);
            s2.x += fmaxf(a2.x + p2.x, 0.f) + fmaxf(a2.x + q2.x, 0.f);
            s2.y += fmaxf(a2.y + p2.y, 0.f) + fmaxf(a2.y + q2.y, 0.f);
            s2.z += fmaxf(a2.z + p2.z, 0.f) + fmaxf(a2.z + q2.z, 0.f);
            s2.w += fmaxf(a2.w + p2.w, 0.f) + fmaxf(a2.w + q2.w, 0.f);
            s3.x += fmaxf(a3.x + p3.x, 0.f) + fmaxf(a3.x + q3.x, 0.f);
            s3.y += fmaxf(a3.y + p3.y, 0.f) + fmaxf(a3.y + q3.y, 0.f);
            s3.z += fmaxf(a3.z + p3.z, 0.f) + fmaxf(a3.z + q3.z, 0.f);
            s3.w += fmaxf(a3.w + p3.w, 0.f) + fmaxf(a3.w + q3.w, 0.f);
        }
        if (t < cnt) {
            int j0 = __shfl_sync(0xFFFFFFFFu, jv, t);
            const float4* B0 = (const float4*)(g_AB + (size_t)j0 * D_AB + D_H) + lane * 4;
            float4 p0 = B0[0], p1 = B0[1], p2 = B0[2], p3 = B0[3];
            s0.x += fmaxf(a0.x + p0.x, 0.f); s0.y += fmaxf(a0.y + p0.y, 0.f);
            s0.z += fmaxf(a0.z + p0.z, 0.f); s0.w += fmaxf(a0.w + p0.w, 0.f);
            s1.x += fmaxf(a1.x + p1.x, 0.f); s1.y += fmaxf(a1.y + p1.y, 0.f);
            s1.z += fmaxf(a1.z + p1.z, 0.f); s1.w += fmaxf(a1.w + p1.w, 0.f);
            s2.x += fmaxf(a2.x + p2.x, 0.f); s2.y += fmaxf(a2.y + p2.y, 0.f);
            s2.z += fmaxf(a2.z + p2.z, 0.f); s2.w += fmaxf(a2.w + p2.w, 0.f);
            s3.x += fmaxf(a3.x + p3.x, 0.f); s3.y += fmaxf(a3.y + p3.y, 0.f);
            s3.z += fmaxf(a3.z + p3.z, 0.f); s3.w += fmaxf(a3.w + p3.w, 0.f);
        }
    }

    // pack to bf16 hi/lo words: 16 floats -> 8 hi + 8 lo words
    uint4 h0, h1, l0, l1;
    split2(s0.x, s0.y, h0.x, l0.x); split2(s0.z, s0.w, h0.y, l0.y);
    split2(s1.x, s1.y, h0.z, l0.z); split2(s1.z, s1.w, h0.w, l0.w);
    split2(s2.x, s2.y, h1.x, l1.x); split2(s2.z, s2.w, h1.y, l1.y);
    split2(s3.x, s3.y, h1.z, l1.z); split2(s3.z, s3.w, h1.w, l1.w);
    uint4* SH = (uint4*)(g_Shi + (size_t)gw * (D_H / 2)) + lane * 2;
    uint4* SL = (uint4*)(g_Slo + (size_t)gw * (D_H / 2)) + lane * 2;
    SH[0] = h0; SH[1] = h1;
    SL[0] = l0; SL[1] = l1;
}

// ---------------- launcher --------------------------------------------------
extern "C" void kernel_launch(void* const* d_in, const int* in_sizes, int n_in,
                              void* d_out, int out_size) {
    const float* x   = (const float*)d_in[0];
    const void*  ei  = d_in[1];
    const float* W1  = (const float*)d_in[2];
    const float* b1  = (const float*)d_in[3];
    const float* W2  = (const float*)d_in[4];
    const float* b2  = (const float*)d_in[5];
    float* out = (float*)d_out;

    cudaFuncSetAttribute(tc_gemm_kernel,
                         cudaFuncAttributeMaxDynamicSharedMemorySize, GEMM_DYNSMEM);

    detect_dtype_kernel<<<1, 32>>>((const unsigned*)ei);
    build_w1t_kernel<<<(D_AB * (D_F / 2) + 255) / 256, 256>>>(W1, b1);
    build_w2t_kernel<<<(D_O * (D_H / 2) + 255) / 256, 256>>>(W2);
    zero_counts_kernel<<<(N_NODES + 255) / 256, 256>>>();
    hist_kernel<<<(N_EDGES + 255) / 256, 256>>>(ei);
    scan_kernel<<<1, 1024>>>();
    scatter_kernel<<<(N_EDGES + 255) / 256, 256>>>(ei);

    float *gAB, *gB1;
    uint32_t *gW1h, *gW1l, *gW2h, *gW2l, *gSh, *gSl;
    cudaGetSymbolAddress((void**)&gAB,  g_AB);
    cudaGetSymbolAddress((void**)&gB1,  g_bias1);
    cudaGetSymbolAddress((void**)&gW1h, g_WT1hi);
    cudaGetSymbolAddress((void**)&gW1l, g_WT1lo);
    cudaGetSymbolAddress((void**)&gW2h, g_WT2hi);
    cudaGetSymbolAddress((void**)&gW2l, g_WT2lo);
    cudaGetSymbolAddress((void**)&gSh,  g_Shi);
    cudaGetSymbolAddress((void**)&gSl,  g_Slo);

    // GEMM1: AB[50000,1024] = x[50000,256] @ WT1^T (+bias_cat)
    {
        dim3 grid(D_AB / 128, (N_NODES + 127) / 128);
        tc_gemm_kernel<<<grid, 256, GEMM_DYNSMEM>>>(
            x, nullptr, nullptr, 0, gW1h, gW1l,
            gAB, N_NODES, D_F, D_AB, gB1, 0);
    }

    aggregate_kernel<<<(N_NODES * 32 + 255) / 256, 256>>>();

    // GEMM2: out[50000,256] = S[50000,512] @ WT2^T + deg*b2
    {
        dim3 grid(D_O / 128, (N_NODES + 127) / 128);
        tc_gemm_kernel<<<grid, 256, GEMM_DYNSMEM>>>(
            nullptr, gSh, gSl, 1, gW2h, gW2l,
            out, N_NODES, D_H, D_O, b2, 1);
    }
}

// round 5
// speedup vs baseline: 1.4350x; 1.0484x over previous
#include <cuda_runtime.h>
#include <cuda_bf16.h>
#include <cstdint>

#define N_NODES 50000
#define N_EDGES 800000
#define D_F 256
#define D_H 512
#define D_O 256
#define D_AB 1024   // cols 0..511 = A part (x@(W1a-W1b)+b1), 512..1023 = B part (x@W1b)

// ---------------- scratch (static device allocations; no cudaMalloc) -------
__device__ uint32_t g_WT1hi[D_AB * (D_F / 2)];     // packed bf16 pairs, K-major
__device__ uint32_t g_WT1lo[D_AB * (D_F / 2)];
__device__ uint32_t g_WT2hi[D_O * (D_H / 2)];
__device__ uint32_t g_WT2lo[D_O * (D_H / 2)];
__device__ float    g_bias1[D_AB];
__device__ float    g_AB[N_NODES * D_AB];          // 204.8 MB fp32
__device__ uint32_t g_Shi[N_NODES * (D_H / 2)];    // 51.2 MB packed bf16
__device__ uint32_t g_Slo[N_NODES * (D_H / 2)];
__device__ int      g_counts[N_NODES];
__device__ int      g_offsets[N_NODES + 1];
__device__ int      g_cursor[N_NODES];
__device__ int      g_scol[N_EDGES];
__device__ int      g_idx64;

// ---------------- helpers ---------------------------------------------------
__device__ __forceinline__ void split2(float v0, float v1, uint32_t& hw, uint32_t& lw) {
    __nv_bfloat16 h0 = __float2bfloat16_rn(v0);
    __nv_bfloat16 h1 = __float2bfloat16_rn(v1);
    float r0 = v0 - __bfloat162float(h0);
    float r1 = v1 - __bfloat162float(h1);
    __nv_bfloat16 l0 = __float2bfloat16_rn(r0);
    __nv_bfloat16 l1 = __float2bfloat16_rn(r1);
    hw = (uint32_t)__bfloat16_as_ushort(h0) | ((uint32_t)__bfloat16_as_ushort(h1) << 16);
    lw = (uint32_t)__bfloat16_as_ushort(l0) | ((uint32_t)__bfloat16_as_ushort(l1) << 16);
}
__device__ __forceinline__ void mma_bf16(float* d, const uint32_t* a, const uint32_t* b) {
    asm volatile(
        "mma.sync.aligned.m16n8k16.row.col.f32.bf16.bf16.f32 "
        "{%0,%1,%2,%3}, {%4,%5,%6,%7}, {%8,%9}, {%0,%1,%2,%3};\n"
        : "+f"(d[0]), "+f"(d[1]), "+f"(d[2]), "+f"(d[3])
        : "r"(a[0]), "r"(a[1]), "r"(a[2]), "r"(a[3]), "r"(b[0]), "r"(b[1]));
}
__device__ __forceinline__ void ldsm_x4(uint32_t* r, uint32_t saddr) {
    asm volatile("ldmatrix.sync.aligned.m8n8.x4.shared.b16 {%0,%1,%2,%3}, [%4];"
                 : "=r"(r[0]), "=r"(r[1]), "=r"(r[2]), "=r"(r[3]) : "r"(saddr));
}
__device__ __forceinline__ uint32_t smem_u32(const void* p) {
    uint32_t a;
    asm("{ .reg .u64 t; cvta.to.shared.u64 t, %1; cvt.u32.u64 %0, t; }" : "=r"(a) : "l"(p));
    return a;
}

// ---------------- edge-index dtype detection -------------------------------
__global__ void detect_dtype_kernel(const unsigned* ei) {
    unsigned acc = 0;
    for (int k = threadIdx.x; k < 512; k += 32) acc |= ei[2 * k + 1];
    #pragma unroll
    for (int o = 16; o > 0; o >>= 1) acc |= __shfl_xor_sync(0xFFFFFFFFu, acc, o);
    if (threadIdx.x == 0) g_idx64 = (acc == 0) ? 1 : 0;
}
__device__ __forceinline__ int load_eidx(const void* ei, int is64, long long pos) {
    return is64 ? (int)((const long long*)ei)[pos] : ((const int*)ei)[pos];
}

// ---------------- weight prep: K-major packed bf16 hi/lo -------------------
__global__ void build_w1t_kernel(const float* __restrict__ W1, const float* __restrict__ b1) {
    int idx = blockIdx.x * blockDim.x + threadIdx.x;
    if (idx < D_AB * (D_F / 2)) {
        int n  = idx >> 7;
        int kw = idx & 127;
        int k0 = kw * 2;
        float v0, v1;
        if (n < D_H) {
            v0 = W1[k0 * D_H + n]       - W1[(k0 + D_F) * D_H + n];
            v1 = W1[(k0 + 1) * D_H + n] - W1[(k0 + 1 + D_F) * D_H + n];
        } else {
            v0 = W1[(k0 + D_F) * D_H + (n - D_H)];
            v1 = W1[(k0 + 1 + D_F) * D_H + (n - D_H)];
        }
        uint32_t hw, lw;
        split2(v0, v1, hw, lw);
        g_WT1hi[idx] = hw; g_WT1lo[idx] = lw;
    }
    if (idx < D_AB) g_bias1[idx] = (idx < D_H) ? b1[idx] : 0.f;
}
__global__ void build_w2t_kernel(const float* __restrict__ W2) {
    int idx = blockIdx.x * blockDim.x + threadIdx.x;
    if (idx < D_O * (D_H / 2)) {
        int n  = idx >> 8;
        int kw = idx & 255;
        float v0 = W2[(2 * kw) * D_O + n];
        float v1 = W2[(2 * kw + 1) * D_O + n];
        uint32_t hw, lw;
        split2(v0, v1, hw, lw);
        g_WT2hi[idx] = hw; g_WT2lo[idx] = lw;
    }
}

// ---------------- counting sort of edges by center node --------------------
__global__ void zero_counts_kernel() {
    int i = blockIdx.x * blockDim.x + threadIdx.x;
    if (i < N_NODES) g_counts[i] = 0;
}
__global__ void hist_kernel(const void* __restrict__ ei) {
    int e = blockIdx.x * blockDim.x + threadIdx.x;
    if (e >= N_EDGES) return;
    int r = load_eidx(ei, g_idx64, e);
    atomicAdd(&g_counts[r], 1);
}
__global__ void scan_kernel() {
    __shared__ int sh[1024];
    const int PER = 49;
    int t = threadIdx.x;
    int base = t * PER;
    int sum = 0;
    for (int j = 0; j < PER; j++) {
        int idx = base + j;
        if (idx < N_NODES) sum += g_counts[idx];
    }
    sh[t] = sum;
    __syncthreads();
    #pragma unroll
    for (int off = 1; off < 1024; off <<= 1) {
        int add = (t >= off) ? sh[t - off] : 0;
        __syncthreads();
        sh[t] += add;
        __syncthreads();
    }
    int run = sh[t] - sum;
    for (int j = 0; j < PER; j++) {
        int idx = base + j;
        if (idx < N_NODES) {
            g_offsets[idx] = run;
            g_cursor[idx]  = run;
            run += g_counts[idx];
        }
    }
    if (t == 1023) g_offsets[N_NODES] = run;
}
__global__ void scatter_kernel(const void* __restrict__ ei) {
    int e = blockIdx.x * blockDim.x + threadIdx.x;
    if (e >= N_EDGES) return;
    int is64 = g_idx64;
    int r = load_eidx(ei, is64, e);
    int c = load_eidx(ei, is64, (long long)N_EDGES + e);
    int pos = atomicAdd(&g_cursor[r], 1);
    g_scol[pos] = c;
}

// =================== mma.sync bf16 GEMM (error-compensated 3-term) =========
// C[M,N] = A[M,K] @ B^T, B packed bf16 hi/lo [N][K/2] K-major words.
// A: fp32 [M][K] (split on the fly) or packed hi/lo [M][K/2].
// CTA tile 128x128, BK=32 (16 words). 8 warps 2(M)x4(N), warp tile 64x32.
// ldmatrix fragment loads; staged smem epilogue for coalesced C writes.
// mode 0: C += bias[col]   mode 1: C += deg[row]*bias[col]
#define KWC 16
#define STW 20
#define TILE_W (128 * STW)
#define STAGE_W (4 * TILE_W)
#define CSTRIDE 132
#define GEMM_DYNSMEM (2 * STAGE_W * 4)   // 81920 B (>= 128*132*4 = 67584 for epi)

__global__ void __launch_bounds__(256) tc_gemm_kernel(
    const float* __restrict__ Af,
    const uint32_t* __restrict__ Ahi, const uint32_t* __restrict__ Alo, int aPacked,
    const uint32_t* __restrict__ Bhi, const uint32_t* __restrict__ Blo,
    float* __restrict__ C, int M, int K, int ldc,
    const float* __restrict__ bias, int mode)
{
    extern __shared__ uint32_t smw[];
    int tid = threadIdx.x;
    int wid = tid >> 5;
    int lane = tid & 31;
    int warpM = wid & 1;
    int warpN = wid >> 1;
    int blockRow = blockIdx.y * 128;
    int blockCol = blockIdx.x * 128;
    const int Kw = K >> 1;
    const int nch = K >> 5;

    float acc[4][4][4];
    #pragma unroll
    for (int mt = 0; mt < 4; mt++)
        #pragma unroll
        for (int nt = 0; nt < 4; nt++)
            #pragma unroll
            for (int r = 0; r < 4; r++) acc[mt][nt][r] = 0.f;

    // gmem load mapping: each thread owns 8 words (16 floats) of one row
    int ldRow = tid >> 1;
    int ldHalf = tid & 1;
    int so = ldRow * STW + ldHalf * 8;
    int grow = blockRow + ldRow;
    bool rowOK = grow < M;
    int brow = blockCol + ldRow;

    float4 ra[4];
    uint4 pah[2], pal[2];
    uint4 pbh[2], pbl[2];

    auto storeA_fp32 = [&](uint32_t* base) {
        uint32_t* sAhi = base;
        uint32_t* sAlo = base + TILE_W;
        uint4 hh0, hh1, ll0, ll1;
        split2(ra[0].x, ra[0].y, hh0.x, ll0.x);
        split2(ra[0].z, ra[0].w, hh0.y, ll0.y);
        split2(ra[1].x, ra[1].y, hh0.z, ll0.z);
        split2(ra[1].z, ra[1].w, hh0.w, ll0.w);
        split2(ra[2].x, ra[2].y, hh1.x, ll1.x);
        split2(ra[2].z, ra[2].w, hh1.y, ll1.y);
        split2(ra[3].x, ra[3].y, hh1.z, ll1.z);
        split2(ra[3].z, ra[3].w, hh1.w, ll1.w);
        *(uint4*)(sAhi + so) = hh0; *(uint4*)(sAhi + so + 4) = hh1;
        *(uint4*)(sAlo + so) = ll0; *(uint4*)(sAlo + so + 4) = ll1;
    };
    auto storeA_packed = [&](uint32_t* base) {
        uint32_t* sAhi = base;
        uint32_t* sAlo = base + TILE_W;
        *(uint4*)(sAhi + so) = pah[0]; *(uint4*)(sAhi + so + 4) = pah[1];
        *(uint4*)(sAlo + so) = pal[0]; *(uint4*)(sAlo + so + 4) = pal[1];
    };
    auto storeB = [&](uint32_t* base) {
        uint32_t* sBhi = base + 2 * TILE_W;
        uint32_t* sBlo = base + 3 * TILE_W;
        *(uint4*)(sBhi + so) = pbh[0]; *(uint4*)(sBhi + so + 4) = pbh[1];
        *(uint4*)(sBlo + so) = pbl[0]; *(uint4*)(sBlo + so + 4) = pbl[1];
    };
    auto fetch = [&](int c) {
        if (aPacked) {
            if (rowOK) {
                const uint4* ph = (const uint4*)(Ahi + (size_t)grow * Kw + c * KWC + ldHalf * 8);
                const uint4* pl = (const uint4*)(Alo + (size_t)grow * Kw + c * KWC + ldHalf * 8);
                pah[0] = ph[0]; pah[1] = ph[1];
                pal[0] = pl[0]; pal[1] = pl[1];
            } else {
                pah[0] = pah[1] = pal[0] = pal[1] = make_uint4(0, 0, 0, 0);
            }
        } else {
            if (rowOK) {
                const float4* p = (const float4*)(Af + (size_t)grow * K + c * 32 + ldHalf * 16);
                ra[0] = p[0]; ra[1] = p[1]; ra[2] = p[2]; ra[3] = p[3];
            } else {
                ra[0] = ra[1] = ra[2] = ra[3] = make_float4(0.f, 0.f, 0.f, 0.f);
            }
        }
        const uint4* qh = (const uint4*)(Bhi + (size_t)brow * Kw + c * KWC + ldHalf * 8);
        const uint4* ql = (const uint4*)(Blo + (size_t)brow * Kw + c * KWC + ldHalf * 8);
        pbh[0] = qh[0]; pbh[1] = qh[1];
        pbl[0] = ql[0]; pbl[1] = ql[1];
    };

    fetch(0);
    if (aPacked) storeA_packed(smw); else storeA_fp32(smw);
    storeB(smw);
    __syncthreads();

    // ldmatrix lane address components (word units)
    uint32_t smem_base_u = smem_u32(smw);
    int aLaneRow = (lane & 7) + ((lane >> 3) & 1) * 8;   // + warpM*64 + mt*16
    int aLaneColW = (lane >> 4) * 4;                     // + ks*8
    int bLaneRow = (lane & 7) + (lane >> 4) * 8;         // + warpN*32 + pair*16
    int bLaneColW = ((lane >> 3) & 1) * 4;               // + ks*8
    uint32_t aAddr0 = smem_base_u + ((warpM * 64 + aLaneRow) * STW + aLaneColW) * 4;
    uint32_t bAddr0 = smem_base_u + ((warpN * 32 + bLaneRow) * STW + bLaneColW) * 4
                      + 2 * TILE_W * 4;                  // Bhi tile base

    for (int c = 0; c < nch; c++) {
        if (c + 1 < nch) fetch(c + 1);

        uint32_t stageOff = (uint32_t)(c & 1) * STAGE_W * 4;
        #pragma unroll
        for (int ks = 0; ks < 2; ks++) {
            uint32_t kOff = stageOff + ks * 32;          // ks*8 words
            uint32_t ahi[4][4], alo[4][4], bhi[2][4], blo[2][4];
            #pragma unroll
            for (int mt = 0; mt < 4; mt++) {
                uint32_t a = aAddr0 + kOff + mt * (16 * STW * 4);
                ldsm_x4(ahi[mt], a);
                ldsm_x4(alo[mt], a + TILE_W * 4);
            }
            #pragma unroll
            for (int p = 0; p < 2; p++) {
                uint32_t b = bAddr0 + kOff + p * (16 * STW * 4);
                ldsm_x4(bhi[p], b);
                ldsm_x4(blo[p], b + TILE_W * 4);
            }
            #pragma unroll
            for (int mt = 0; mt < 4; mt++)
                #pragma unroll
                for (int nt = 0; nt < 4; nt++) {
                    const uint32_t* bh = &bhi[nt >> 1][(nt & 1) * 2];
                    const uint32_t* bl = &blo[nt >> 1][(nt & 1) * 2];
                    mma_bf16(acc[mt][nt], ahi[mt], bh);
                    mma_bf16(acc[mt][nt], ahi[mt], bl);
                    mma_bf16(acc[mt][nt], alo[mt], bh);
                }
        }

        if (c + 1 < nch) {
            __syncthreads();
            uint32_t* nbase = smw + ((c + 1) & 1) * STAGE_W;
            if (aPacked) storeA_packed(nbase); else storeA_fp32(nbase);
            storeB(nbase);
            __syncthreads();
        }
    }

    // ---- staged epilogue: acc -> smem (fp32) -> coalesced gmem ----
    __syncthreads();
    float* cs = (float*)smw;
    #pragma unroll
    for (int mt = 0; mt < 4; mt++) {
        int r0 = warpM * 64 + mt * 16 + (lane >> 2);
        #pragma unroll
        for (int nt = 0; nt < 4; nt++) {
            int col = warpN * 32 + nt * 8 + (lane & 3) * 2;
            *(float2*)(cs + r0 * CSTRIDE + col) = make_float2(acc[mt][nt][0], acc[mt][nt][1]);
            *(float2*)(cs + (r0 + 8) * CSTRIDE + col) = make_float2(acc[mt][nt][2], acc[mt][nt][3]);
        }
    }
    __syncthreads();
    #pragma unroll
    for (int kk = 0; kk < 16; kk++) {
        int idx = tid + kk * 256;
        int row = idx >> 5;
        int c4 = (idx & 31) * 4;
        int gr = blockRow + row;
        if (gr < M) {
            float4 v = *(float4*)(cs + row * CSTRIDE + c4);
            float4 bv = *(const float4*)(bias + blockCol + c4);
            if (mode == 0) {
                v.x += bv.x; v.y += bv.y; v.z += bv.z; v.w += bv.w;
            } else {
                float degf = (float)(g_offsets[gr + 1] - g_offsets[gr]);
                v.x += degf * bv.x; v.y += degf * bv.y;
                v.z += degf * bv.z; v.w += degf * bv.w;
            }
            *(float4*)(C + (size_t)gr * ldc + blockCol + c4) = v;
        }
    }
}

// ---------------- aggregation: S_i = sum_j relu(A_i + B_j), warp per node --
__global__ __launch_bounds__(256) void aggregate_kernel() {
    int gw = (blockIdx.x * blockDim.x + threadIdx.x) >> 5;
    int lane = threadIdx.x & 31;
    if (gw >= N_NODES) return;

    const float4* Ai = (const float4*)(g_AB + (size_t)gw * D_AB) + lane * 4;
    float4 a0 = Ai[0], a1 = Ai[1], a2 = Ai[2], a3 = Ai[3];
    float4 s0 = make_float4(0, 0, 0, 0), s1 = s0, s2 = s0, s3 = s0;

    int beg = g_offsets[gw], end = g_offsets[gw + 1];
    for (int b = beg; b < end; b += 32) {
        int jv = (b + lane < end) ? g_scol[b + lane] : 0;
        int cnt = min(32, end - b);
        int t = 0;
        for (; t + 1 < cnt; t += 2) {
            int j0 = __shfl_sync(0xFFFFFFFFu, jv, t);
            int j1 = __shfl_sync(0xFFFFFFFFu, jv, t + 1);
            const float4* B0 = (const float4*)(g_AB + (size_t)j0 * D_AB + D_H) + lane * 4;
            const float4* B1 = (const float4*)(g_AB + (size_t)j1 * D_AB + D_H) + lane * 4;
            float4 p0 = B0[0], p1 = B0[1], p2 = B0[2], p3 = B0[3];
            float4 q0 = B1[0], q1 = B1[1], q2 = B1[2], q3 = B1[3];
            s0.x += fmaxf(a0.x + p0.x, 0.f) + fmaxf(a0.x + q0.x, 0.f);
            s0.y += fmaxf(a0.y + p0.y, 0.f) + fmaxf(a0.y + q0.y, 0.f);
            s0.z += fmaxf(a0.z + p0.z, 0.f) + fmaxf(a0.z + q0.z, 0.f);
            s0.w += fmaxf(a0.w + p0.w, 0.f) + fmaxf(a0.w + q0.w, 0.f);
            s1.x += fmaxf(a1.x + p1.x, 0.f) + fmaxf(a1.x + q1.x, 0.f);
            s1.y += fmaxf(a1.y + p1.y, 0.f) + fmaxf(a1.y + q1.y, 0.f);
            s1.z += fmaxf(a1.z + p1.z, 0.f) + fmaxf(a1.z + q1.z, 0.f);
            s1.w += fmaxf(a1.w + p1.w, 0.f) + fmaxf(a1.w + q1.w, 0.f);
            s2.x += fmaxf(a2.x + p2.x, 0.f) + fmaxf(a2.x + q2.x, 0.f);
            s2.y += fmaxf(a2.y + p2.y, 0.f) + fmaxf(a2.y + q2.y, 0.f);
            s2.z += fmaxf(a2.z + p2.z, 0.f) + fmaxf(a2.z + q2.z, 0.f);
            s2.w += fmaxf(a2.w + p2.w, 0.f) + fmaxf(a2.w + q2.w, 0.f);
            s3.x += fmaxf(a3.x + p3.x, 0.f) + fmaxf(a3.x + q3.x, 0.f);
            s3.y += fmaxf(a3.y + p3.y, 0.f) + fmaxf(a3.y + q3.y, 0.f);
            s3.z += fmaxf(a3.z + p3.z, 0.f) + fmaxf(a3.z + q3.z, 0.f);
            s3.w += fmaxf(a3.w + p3.w, 0.f) + fmaxf(a3.w + q3.w, 0.f);
        }
        if (t < cnt) {
            int j0 = __shfl_sync(0xFFFFFFFFu, jv, t);
            const float4* B0 = (const float4*)(g_AB + (size_t)j0 * D_AB + D_H) + lane * 4;
            float4 p0 = B0[0], p1 = B0[1], p2 = B0[2], p3 = B0[3];
            s0.x += fmaxf(a0.x + p0.x, 0.f); s0.y += fmaxf(a0.y + p0.y, 0.f);
            s0.z += fmaxf(a0.z + p0.z, 0.f); s0.w += fmaxf(a0.w + p0.w, 0.f);
            s1.x += fmaxf(a1.x + p1.x, 0.f); s1.y += fmaxf(a1.y + p1.y, 0.f);
            s1.z += fmaxf(a1.z + p1.z, 0.f); s1.w += fmaxf(a1.w + p1.w, 0.f);
            s2.x += fmaxf(a2.x + p2.x, 0.f); s2.y += fmaxf(a2.y + p2.y, 0.f);
            s2.z += fmaxf(a2.z + p2.z, 0.f); s2.w += fmaxf(a2.w + p2.w, 0.f);
            s3.x += fmaxf(a3.x + p3.x, 0.f); s3.y += fmaxf(a3.y + p3.y, 0.f);
            s3.z += fmaxf(a3.z + p3.z, 0.f); s3.w += fmaxf(a3.w + p3.w, 0.f);
        }
    }

    uint4 h0, h1, l0, l1;
    split2(s0.x, s0.y, h0.x, l0.x); split2(s0.z, s0.w, h0.y, l0.y);
    split2(s1.x, s1.y, h0.z, l0.z); split2(s1.z, s1.w, h0.w, l0.w);
    split2(s2.x, s2.y, h1.x, l1.x); split2(s2.z, s2.w, h1.y, l1.y);
    split2(s3.x, s3.y, h1.z, l1.z); split2(s3.z, s3.w, h1.w, l1.w);
    uint4* SH = (uint4*)(g_Shi + (size_t)gw * (D_H / 2)) + lane * 2;
    uint4* SL = (uint4*)(g_Slo + (size_t)gw * (D_H / 2)) + lane * 2;
    SH[0] = h0; SH[1] = h1;
    SL[0] = l0; SL[1] = l1;
}

// ---------------- launcher --------------------------------------------------
extern "C" void kernel_launch(void* const* d_in, const int* in_sizes, int n_in,
                              void* d_out, int out_size) {
    const float* x   = (const float*)d_in[0];
    const void*  ei  = d_in[1];
    const float* W1  = (const float*)d_in[2];
    const float* b1  = (const float*)d_in[3];
    const float* W2  = (const float*)d_in[4];
    const float* b2  = (const float*)d_in[5];
    float* out = (float*)d_out;

    cudaFuncSetAttribute(tc_gemm_kernel,
                         cudaFuncAttributeMaxDynamicSharedMemorySize, GEMM_DYNSMEM);

    float *gAB, *gB1;
    uint32_t *gW1h, *gW1l, *gW2h, *gW2l, *gSh, *gSl;
    cudaGetSymbolAddress((void**)&gAB,  g_AB);
    cudaGetSymbolAddress((void**)&gB1,  g_bias1);
    cudaGetSymbolAddress((void**)&gW1h, g_WT1hi);
    cudaGetSymbolAddress((void**)&gW1l, g_WT1lo);
    cudaGetSymbolAddress((void**)&gW2h, g_WT2hi);
    cudaGetSymbolAddress((void**)&gW2l, g_WT2lo);
    cudaGetSymbolAddress((void**)&gSh,  g_Shi);
    cudaGetSymbolAddress((void**)&gSl,  g_Slo);

    // launch order chosen so GEMM1 is the 4th launch (ncu capture slot)
    detect_dtype_kernel<<<1, 32>>>((const unsigned*)ei);
    build_w1t_kernel<<<(D_AB * (D_F / 2) + 255) / 256, 256>>>(W1, b1);
    build_w2t_kernel<<<(D_O * (D_H / 2) + 255) / 256, 256>>>(W2);

    // GEMM1 (4th): AB[50000,1024] = x @ WT1^T (+bias_cat)
    {
        dim3 grid(D_AB / 128, (N_NODES + 127) / 128);
        tc_gemm_kernel<<<grid, 256, GEMM_DYNSMEM>>>(
            x, nullptr, nullptr, 0, gW1h, gW1l,
            gAB, N_NODES, D_F, D_AB, gB1, 0);
    }

    zero_counts_kernel<<<(N_NODES + 255) / 256, 256>>>();
    hist_kernel<<<(N_EDGES + 255) / 256, 256>>>(ei);
    scan_kernel<<<1, 1024>>>();
    scatter_kernel<<<(N_EDGES + 255) / 256, 256>>>(ei);

    aggregate_kernel<<<(N_NODES * 32 + 255) / 256, 256>>>();

    // GEMM2: out[50000,256] = S @ WT2^T + deg*b2
    {
        dim3 grid(D_O / 128, (N_NODES + 127) / 128);
        tc_gemm_kernel<<<grid, 256, GEMM_DYNSMEM>>>(
            nullptr, gSh, gSl, 1, gW2h, gW2l,
            out, N_NODES, D_H, D_O, b2, 1);
    }
}

// round 6
// speedup vs baseline: 1.6793x; 1.1702x over previous
#include <cuda_runtime.h>
#include <cuda_bf16.h>
#include <cstdint>

#define N_NODES 50000
#define N_PAD   50048      // padded to multiple of 128
#define N_EDGES 800000
#define D_F 256
#define D_H 512
#define D_O 256
#define D_AB 1024

// ---------------- scratch (static device allocations; no cudaMalloc) -------
__device__ uint32_t g_Xhi[N_PAD * (D_F / 2)];      // packed bf16 x hi/lo
__device__ uint32_t g_Xlo[N_PAD * (D_F / 2)];
__device__ uint32_t g_WT1hi[D_AB * (D_F / 2)];
__device__ uint32_t g_WT1lo[D_AB * (D_F / 2)];
__device__ uint32_t g_WT2hi[D_O * (D_H / 2)];
__device__ uint32_t g_WT2lo[D_O * (D_H / 2)];
__device__ float    g_bias1[D_AB];
__device__ float    g_AB[N_NODES * D_AB];          // 204.8 MB fp32
__device__ uint32_t g_Shi[N_PAD * (D_H / 2)];
__device__ uint32_t g_Slo[N_PAD * (D_H / 2)];
__device__ int      g_counts[N_NODES];
__device__ int      g_offsets[N_NODES + 1];
__device__ int      g_cursor[N_NODES];
__device__ int      g_scol[N_EDGES];
__device__ int      g_idx64;

// ---------------- helpers ---------------------------------------------------
__device__ __forceinline__ void split2(float v0, float v1, uint32_t& hw, uint32_t& lw) {
    __nv_bfloat16 h0 = __float2bfloat16_rn(v0);
    __nv_bfloat16 h1 = __float2bfloat16_rn(v1);
    float r0 = v0 - __bfloat162float(h0);
    float r1 = v1 - __bfloat162float(h1);
    __nv_bfloat16 l0 = __float2bfloat16_rn(r0);
    __nv_bfloat16 l1 = __float2bfloat16_rn(r1);
    hw = (uint32_t)__bfloat16_as_ushort(h0) | ((uint32_t)__bfloat16_as_ushort(h1) << 16);
    lw = (uint32_t)__bfloat16_as_ushort(l0) | ((uint32_t)__bfloat16_as_ushort(l1) << 16);
}
__device__ __forceinline__ void mma_bf16(float* d, const uint32_t* a, const uint32_t* b) {
    asm volatile(
        "mma.sync.aligned.m16n8k16.row.col.f32.bf16.bf16.f32 "
        "{%0,%1,%2,%3}, {%4,%5,%6,%7}, {%8,%9}, {%0,%1,%2,%3};\n"
        : "+f"(d[0]), "+f"(d[1]), "+f"(d[2]), "+f"(d[3])
        : "r"(a[0]), "r"(a[1]), "r"(a[2]), "r"(a[3]), "r"(b[0]), "r"(b[1]));
}
__device__ __forceinline__ void ldsm_x4(uint32_t* r, uint32_t saddr) {
    asm volatile("ldmatrix.sync.aligned.m8n8.x4.shared.b16 {%0,%1,%2,%3}, [%4];"
                 : "=r"(r[0]), "=r"(r[1]), "=r"(r[2]), "=r"(r[3]) : "r"(saddr));
}
__device__ __forceinline__ uint32_t smem_u32(const void* p) {
    uint32_t a;
    asm("{ .reg .u64 t; cvta.to.shared.u64 t, %1; cvt.u32.u64 %0, t; }" : "=r"(a) : "l"(p));
    return a;
}
#define CP16(dst, src) \
    asm volatile("cp.async.cg.shared.global [%0], [%1], 16;" :: "r"(dst), "l"(src))
#define CP_COMMIT() asm volatile("cp.async.commit_group;" ::: "memory")
#define CP_WAIT0()  asm volatile("cp.async.wait_group 0;" ::: "memory")

// ---------------- edge-index dtype detection -------------------------------
__global__ void detect_dtype_kernel(const unsigned* ei) {
    unsigned acc = 0;
    for (int k = threadIdx.x; k < 512; k += 32) acc |= ei[2 * k + 1];
    #pragma unroll
    for (int o = 16; o > 0; o >>= 1) acc |= __shfl_xor_sync(0xFFFFFFFFu, acc, o);
    if (threadIdx.x == 0) g_idx64 = (acc == 0) ? 1 : 0;
}
__device__ __forceinline__ int load_eidx(const void* ei, int is64, long long pos) {
    return is64 ? (int)((const long long*)ei)[pos] : ((const int*)ei)[pos];
}

// ---------------- x split: fp32 -> packed bf16 hi/lo ------------------------
__global__ void split_x_kernel(const float* __restrict__ x) {
    int gid = blockIdx.x * blockDim.x + threadIdx.x;
    if (gid >= N_NODES * 32) return;
    int row = gid >> 5, ch = gid & 31;
    const float4* p = (const float4*)(x + (size_t)row * D_F + ch * 8);
    float4 v0 = p[0], v1 = p[1];
    uint4 h, l;
    split2(v0.x, v0.y, h.x, l.x); split2(v0.z, v0.w, h.y, l.y);
    split2(v1.x, v1.y, h.z, l.z); split2(v1.z, v1.w, h.w, l.w);
    *(uint4*)(g_Xhi + (size_t)row * (D_F / 2) + ch * 4) = h;
    *(uint4*)(g_Xlo + (size_t)row * (D_F / 2) + ch * 4) = l;
}

// ---------------- weight prep: K-major packed bf16 hi/lo -------------------
__global__ void build_w1t_kernel(const float* __restrict__ W1, const float* __restrict__ b1) {
    int idx = blockIdx.x * blockDim.x + threadIdx.x;
    if (idx < D_AB * (D_F / 2)) {
        int n  = idx >> 7;
        int kw = idx & 127;
        int k0 = kw * 2;
        float v0, v1;
        if (n < D_H) {
            v0 = W1[k0 * D_H + n]       - W1[(k0 + D_F) * D_H + n];
            v1 = W1[(k0 + 1) * D_H + n] - W1[(k0 + 1 + D_F) * D_H + n];
        } else {
            v0 = W1[(k0 + D_F) * D_H + (n - D_H)];
            v1 = W1[(k0 + 1 + D_F) * D_H + (n - D_H)];
        }
        uint32_t hw, lw;
        split2(v0, v1, hw, lw);
        g_WT1hi[idx] = hw; g_WT1lo[idx] = lw;
    }
    if (idx < D_AB) g_bias1[idx] = (idx < D_H) ? b1[idx] : 0.f;
}
__global__ void build_w2t_kernel(const float* __restrict__ W2) {
    int idx = blockIdx.x * blockDim.x + threadIdx.x;
    if (idx < D_O * (D_H / 2)) {
        int n  = idx >> 8;
        int kw = idx & 255;
        float v0 = W2[(2 * kw) * D_O + n];
        float v1 = W2[(2 * kw + 1) * D_O + n];
        uint32_t hw, lw;
        split2(v0, v1, hw, lw);
        g_WT2hi[idx] = hw; g_WT2lo[idx] = lw;
    }
}

// ---------------- counting sort of edges by center node --------------------
__global__ void zero_counts_kernel() {
    int i = blockIdx.x * blockDim.x + threadIdx.x;
    if (i < N_NODES) g_counts[i] = 0;
}
__global__ void hist_kernel(const void* __restrict__ ei) {
    int e = blockIdx.x * blockDim.x + threadIdx.x;
    if (e >= N_EDGES) return;
    int r = load_eidx(ei, g_idx64, e);
    atomicAdd(&g_counts[r], 1);
}
__global__ void scan_kernel() {
    __shared__ int sh[1024];
    const int PER = 49;
    int t = threadIdx.x;
    int base = t * PER;
    int sum = 0;
    for (int j = 0; j < PER; j++) {
        int idx = base + j;
        if (idx < N_NODES) sum += g_counts[idx];
    }
    sh[t] = sum;
    __syncthreads();
    #pragma unroll
    for (int off = 1; off < 1024; off <<= 1) {
        int add = (t >= off) ? sh[t - off] : 0;
        __syncthreads();
        sh[t] += add;
        __syncthreads();
    }
    int run = sh[t] - sum;
    for (int j = 0; j < PER; j++) {
        int idx = base + j;
        if (idx < N_NODES) {
            g_offsets[idx] = run;
            g_cursor[idx]  = run;
            run += g_counts[idx];
        }
    }
    if (t == 1023) g_offsets[N_NODES] = run;
}
__global__ void scatter_kernel(const void* __restrict__ ei) {
    int e = blockIdx.x * blockDim.x + threadIdx.x;
    if (e >= N_EDGES) return;
    int is64 = g_idx64;
    int r = load_eidx(ei, is64, e);
    int c = load_eidx(ei, is64, (long long)N_EDGES + e);
    int pos = atomicAdd(&g_cursor[r], 1);
    g_scol[pos] = c;
}

// =================== mma.sync bf16 GEMM (error-compensated 3-term) =========
// All operands packed bf16 hi/lo [rows][K/2] K-major words (rows padded).
// CTA tile 128x128, BK=32 (16 words). 8 warps 2(M)x4(N), warp tile 64x32.
// cp.async 2-stage pipeline; ldmatrix fragments; staged smem epilogue.
// mode 0: C += bias[col]   mode 1: C += deg[row]*bias[col]
#define KWC 16
#define STW 20
#define TILE_W (128 * STW)
#define STAGE_W (4 * TILE_W)
#define CSTRIDE 132
#define GEMM_DYNSMEM (2 * STAGE_W * 4)   // 81920 B

__global__ void __launch_bounds__(256, 2) tc_gemm_kernel(
    const uint32_t* __restrict__ Ahi, const uint32_t* __restrict__ Alo,
    const uint32_t* __restrict__ Bhi, const uint32_t* __restrict__ Blo,
    float* __restrict__ C, int M, int K, int ldc,
    const float* __restrict__ bias, int mode)
{
    extern __shared__ uint32_t smw[];
    int tid = threadIdx.x;
    int wid = tid >> 5;
    int lane = tid & 31;
    int warpM = wid & 1;
    int warpN = wid >> 1;
    int blockRow = blockIdx.y * 128;
    int blockCol = blockIdx.x * 128;
    const int Kw = K >> 1;
    const int nch = K >> 5;

    float acc[4][4][4];
    #pragma unroll
    for (int mt = 0; mt < 4; mt++)
        #pragma unroll
        for (int nt = 0; nt < 4; nt++)
            #pragma unroll
            for (int r = 0; r < 4; r++) acc[mt][nt][r] = 0.f;

    uint32_t sbase = smem_u32(smw);
    int ldRow = tid >> 1;
    int ldHalf = tid & 1;
    uint32_t soB = (uint32_t)(ldRow * STW + ldHalf * 8) * 4;   // byte offset in tile
    size_t aOff = (size_t)(blockRow + ldRow) * Kw + ldHalf * 8;
    size_t bOff = (size_t)(blockCol + ldRow) * Kw + ldHalf * 8;

    auto issue = [&](int c) {
        uint32_t d = sbase + (uint32_t)(c & 1) * (STAGE_W * 4) + soB;
        const uint32_t* a0 = Ahi + aOff + (size_t)c * KWC;
        const uint32_t* a1 = Alo + aOff + (size_t)c * KWC;
        const uint32_t* b0 = Bhi + bOff + (size_t)c * KWC;
        const uint32_t* b1 = Blo + bOff + (size_t)c * KWC;
        CP16(d, a0);                      CP16(d + 16, a0 + 4);
        CP16(d + TILE_W * 4, a1);         CP16(d + TILE_W * 4 + 16, a1 + 4);
        CP16(d + 2 * TILE_W * 4, b0);     CP16(d + 2 * TILE_W * 4 + 16, b0 + 4);
        CP16(d + 3 * TILE_W * 4, b1);     CP16(d + 3 * TILE_W * 4 + 16, b1 + 4);
        CP_COMMIT();
    };

    issue(0);
    CP_WAIT0();
    __syncthreads();

    // ldmatrix lane address components
    int aLaneRow = (lane & 7) + ((lane >> 3) & 1) * 8;
    int aLaneColW = (lane >> 4) * 4;
    int bLaneRow = (lane & 7) + (lane >> 4) * 8;
    int bLaneColW = ((lane >> 3) & 1) * 4;
    uint32_t aAddr0 = sbase + ((warpM * 64 + aLaneRow) * STW + aLaneColW) * 4;
    uint32_t bAddr0 = sbase + ((warpN * 32 + bLaneRow) * STW + bLaneColW) * 4
                      + 2 * TILE_W * 4;

    for (int c = 0; c < nch; c++) {
        if (c + 1 < nch) issue(c + 1);

        uint32_t stageOff = (uint32_t)(c & 1) * (STAGE_W * 4);
        #pragma unroll
        for (int ks = 0; ks < 2; ks++) {
            uint32_t kOff = stageOff + ks * 32;
            uint32_t ahi[4][4], alo[4][4], bhi[2][4], blo[2][4];
            #pragma unroll
            for (int mt = 0; mt < 4; mt++) {
                uint32_t a = aAddr0 + kOff + mt * (16 * STW * 4);
                ldsm_x4(ahi[mt], a);
                ldsm_x4(alo[mt], a + TILE_W * 4);
            }
            #pragma unroll
            for (int p = 0; p < 2; p++) {
                uint32_t b = bAddr0 + kOff + p * (16 * STW * 4);
                ldsm_x4(bhi[p], b);
                ldsm_x4(blo[p], b + TILE_W * 4);
            }
            #pragma unroll
            for (int mt = 0; mt < 4; mt++)
                #pragma unroll
                for (int nt = 0; nt < 4; nt++) {
                    const uint32_t* bh = &bhi[nt >> 1][(nt & 1) * 2];
                    const uint32_t* bl = &blo[nt >> 1][(nt & 1) * 2];
                    mma_bf16(acc[mt][nt], ahi[mt], bh);
                    mma_bf16(acc[mt][nt], ahi[mt], bl);
                    mma_bf16(acc[mt][nt], alo[mt], bh);
                }
        }

        if (c + 1 < nch) {
            CP_WAIT0();
            __syncthreads();
        }
    }

    // ---- staged epilogue: acc -> smem (fp32) -> coalesced gmem ----
    __syncthreads();
    float* cs = (float*)smw;
    #pragma unroll
    for (int mt = 0; mt < 4; mt++) {
        int r0 = warpM * 64 + mt * 16 + (lane >> 2);
        #pragma unroll
        for (int nt = 0; nt < 4; nt++) {
            int col = warpN * 32 + nt * 8 + (lane & 3) * 2;
            *(float2*)(cs + r0 * CSTRIDE + col) = make_float2(acc[mt][nt][0], acc[mt][nt][1]);
            *(float2*)(cs + (r0 + 8) * CSTRIDE + col) = make_float2(acc[mt][nt][2], acc[mt][nt][3]);
        }
    }
    __syncthreads();
    #pragma unroll
    for (int kk = 0; kk < 16; kk++) {
        int idx = tid + kk * 256;
        int row = idx >> 5;
        int c4 = (idx & 31) * 4;
        int gr = blockRow + row;
        if (gr < M) {
            float4 v = *(float4*)(cs + row * CSTRIDE + c4);
            float4 bv = *(const float4*)(bias + blockCol + c4);
            if (mode == 0) {
                v.x += bv.x; v.y += bv.y; v.z += bv.z; v.w += bv.w;
            } else {
                float degf = (float)(g_offsets[gr + 1] - g_offsets[gr]);
                v.x += degf * bv.x; v.y += degf * bv.y;
                v.z += degf * bv.z; v.w += degf * bv.w;
            }
            *(float4*)(C + (size_t)gr * ldc + blockCol + c4) = v;
        }
    }
}

// ---------------- aggregation: S_i = sum_j relu(A_i + B_j), warp per node --
__global__ __launch_bounds__(256) void aggregate_kernel() {
    int gw = (blockIdx.x * blockDim.x + threadIdx.x) >> 5;
    int lane = threadIdx.x & 31;
    if (gw >= N_NODES) return;

    const float4* Ai = (const float4*)(g_AB + (size_t)gw * D_AB) + lane * 4;
    float4 a0 = Ai[0], a1 = Ai[1], a2 = Ai[2], a3 = Ai[3];
    float4 s0 = make_float4(0, 0, 0, 0), s1 = s0, s2 = s0, s3 = s0;

    int beg = g_offsets[gw], end = g_offsets[gw + 1];
    for (int b = beg; b < end; b += 32) {
        int jv = (b + lane < end) ? g_scol[b + lane] : 0;
        int cnt = min(32, end - b);
        int t = 0;
        for (; t + 1 < cnt; t += 2) {
            int j0 = __shfl_sync(0xFFFFFFFFu, jv, t);
            int j1 = __shfl_sync(0xFFFFFFFFu, jv, t + 1);
            const float4* B0 = (const float4*)(g_AB + (size_t)j0 * D_AB + D_H) + lane * 4;
            const float4* B1 = (const float4*)(g_AB + (size_t)j1 * D_AB + D_H) + lane * 4;
            float4 p0 = B0[0], p1 = B0[1], p2 = B0[2], p3 = B0[3];
            float4 q0 = B1[0], q1 = B1[1], q2 = B1[2], q3 = B1[3];
            s0.x += fmaxf(a0.x + p0.x, 0.f) + fmaxf(a0.x + q0.x, 0.f);
            s0.y += fmaxf(a0.y + p0.y, 0.f) + fmaxf(a0.y + q0.y, 0.f);
            s0.z += fmaxf(a0.z + p0.z, 0.f) + fmaxf(a0.z + q0.z, 0.f);
            s0.w += fmaxf(a0.w + p0.w, 0.f) + fmaxf(a0.w + q0.w, 0.f);
            s1.x += fmaxf(a1.x + p1.x, 0.f) + fmaxf(a1.x + q1.x, 0.f);
            s1.y += fmaxf(a1.y + p1.y, 0.f) + fmaxf(a1.y + q1.y, 0.f);
            s1.z += fmaxf(a1.z + p1.z, 0.f) + fmaxf(a1.z + q1.z, 0.f);
            s1.w += fmaxf(a1.w + p1.w, 0.f) + fmaxf(a1.w + q1.w, 0.f);
            s2.x += fmaxf(a2.x + p2.x, 0.f) + fmaxf(a2.x + q2.x, 0.f);
            s2.y += fmaxf(a2.y + p2.y, 0.f) + fmaxf(a2.y + q2.y, 0.f);
            s2.z += fmaxf(a2.z + p2.z, 0.f) + fmaxf(a2.z + q2.z, 0.f);
            s2.w += fmaxf(a2.w + p2.w, 0.f) + fmaxf(a2.w + q2.w, 0.f);
            s3.x += fmaxf(a3.x + p3.x, 0.f) + fmaxf(a3.x + q3.x, 0.f);
            s3.y += fmaxf(a3.y + p3.y, 0.f) + fmaxf(a3.y + q3.y, 0.f);
            s3.z += fmaxf(a3.z + p3.z, 0.f) + fmaxf(a3.z + q3.z, 0.f);
            s3.w += fmaxf(a3.w + p3.w, 0.f) + fmaxf(a3.w + q3.w, 0.f);
        }
        if (t < cnt) {
            int j0 = __shfl_sync(0xFFFFFFFFu, jv, t);
            const float4* B0 = (const float4*)(g_AB + (size_t)j0 * D_AB + D_H) + lane * 4;
            float4 p0 = B0[0], p1 = B0[1], p2 = B0[2], p3 = B0[3];
            s0.x += fmaxf(a0.x + p0.x, 0.f); s0.y += fmaxf(a0.y + p0.y, 0.f);
            s0.z += fmaxf(a0.z + p0.z, 0.f); s0.w += fmaxf(a0.w + p0.w, 0.f);
            s1.x += fmaxf(a1.x + p1.x, 0.f); s1.y += fmaxf(a1.y + p1.y, 0.f);
            s1.z += fmaxf(a1.z + p1.z, 0.f); s1.w += fmaxf(a1.w + p1.w, 0.f);
            s2.x += fmaxf(a2.x + p2.x, 0.f); s2.y += fmaxf(a2.y + p2.y, 0.f);
            s2.z += fmaxf(a2.z + p2.z, 0.f); s2.w += fmaxf(a2.w + p2.w, 0.f);
            s3.x += fmaxf(a3.x + p3.x, 0.f); s3.y += fmaxf(a3.y + p3.y, 0.f);
            s3.z += fmaxf(a3.z + p3.z, 0.f); s3.w += fmaxf(a3.w + p3.w, 0.f);
        }
    }

    uint4 h0, h1, l0, l1;
    split2(s0.x, s0.y, h0.x, l0.x); split2(s0.z, s0.w, h0.y, l0.y);
    split2(s1.x, s1.y, h0.z, l0.z); split2(s1.z, s1.w, h0.w, l0.w);
    split2(s2.x, s2.y, h1.x, l1.x); split2(s2.z, s2.w, h1.y, l1.y);
    split2(s3.x, s3.y, h1.z, l1.z); split2(s3.z, s3.w, h1.w, l1.w);
    uint4* SH = (uint4*)(g_Shi + (size_t)gw * (D_H / 2)) + lane * 2;
    uint4* SL = (uint4*)(g_Slo + (size_t)gw * (D_H / 2)) + lane * 2;
    SH[0] = h0; SH[1] = h1;
    SL[0] = l0; SL[1] = l1;
}

// ---------------- launcher --------------------------------------------------
extern "C" void kernel_launch(void* const* d_in, const int* in_sizes, int n_in,
                              void* d_out, int out_size) {
    const float* x   = (const float*)d_in[0];
    const void*  ei  = d_in[1];
    const float* W1  = (const float*)d_in[2];
    const float* b1  = (const float*)d_in[3];
    const float* W2  = (const float*)d_in[4];
    const float* b2  = (const float*)d_in[5];
    float* out = (float*)d_out;

    cudaFuncSetAttribute(tc_gemm_kernel,
                         cudaFuncAttributeMaxDynamicSharedMemorySize, GEMM_DYNSMEM);

    float *gAB, *gB1;
    uint32_t *gXh, *gXl, *gW1h, *gW1l, *gW2h, *gW2l, *gSh, *gSl;
    cudaGetSymbolAddress((void**)&gAB,  g_AB);
    cudaGetSymbolAddress((void**)&gB1,  g_bias1);
    cudaGetSymbolAddress((void**)&gXh,  g_Xhi);
    cudaGetSymbolAddress((void**)&gXl,  g_Xlo);
    cudaGetSymbolAddress((void**)&gW1h, g_WT1hi);
    cudaGetSymbolAddress((void**)&gW1l, g_WT1lo);
    cudaGetSymbolAddress((void**)&gW2h, g_WT2hi);
    cudaGetSymbolAddress((void**)&gW2l, g_WT2lo);
    cudaGetSymbolAddress((void**)&gSh,  g_Shi);
    cudaGetSymbolAddress((void**)&gSl,  g_Slo);

    // launch order keeps GEMM1 in the 4th slot (ncu capture)
    detect_dtype_kernel<<<1, 32>>>((const unsigned*)ei);
    split_x_kernel<<<(N_NODES * 32 + 255) / 256, 256>>>(x);
    build_w1t_kernel<<<(D_AB * (D_F / 2) + 255) / 256, 256>>>(W1, b1);

    // GEMM1 (4th): AB[50000,1024] = x @ WT1^T (+bias_cat)
    {
        dim3 grid(D_AB / 128, N_PAD / 128);
        tc_gemm_kernel<<<grid, 256, GEMM_DYNSMEM>>>(
            gXh, gXl, gW1h, gW1l, gAB, N_NODES, D_F, D_AB, gB1, 0);
    }

    zero_counts_kernel<<<(N_NODES + 255) / 256, 256>>>();
    hist_kernel<<<(N_EDGES + 255) / 256, 256>>>(ei);
    scan_kernel<<<1, 1024>>>();
    scatter_kernel<<<(N_EDGES + 255) / 256, 256>>>(ei);

    aggregate_kernel<<<(N_NODES * 32 + 255) / 256, 256>>>();
    build_w2t_kernel<<<(D_O * (D_H / 2) + 255) / 256, 256>>>(W2);

    // GEMM2: out[50000,256] = S @ WT2^T + deg*b2
    {
        dim3 grid(D_O / 128, N_PAD / 128);
        tc_gemm_kernel<<<grid, 256, GEMM_DYNSMEM>>>(
            gSh, gSl, gW2h, gW2l, out, N_NODES, D_H, D_O, b2, 1);
    }
}